// round 14
// baseline (speedup 1.0000x reference)
#include <cuda_runtime.h>
#include <cuda_fp16.h>
#include <math.h>
#include <stdint.h>

// ---------------- problem constants ----------------
#define NTOK  4096
#define LSEQ  1024
#define BATCH 4
#define DM    1024
#define DI    2048
#define DS    16
#define DTR   64
#define XPD   96
#define NEXP  8
#define HEXP  1024
#define KSPL  8

// ---------------- device scratch ----------------
__device__ float g_x [NTOK*DM];
__device__ float g_uz[NTOK*2*DI];
__device__ float g_u [NTOK*DI];
__device__ float g_xp[NTOK*XPD];
__device__ float g_xps[KSPL*NTOK*XPD];
__device__ float g_dt[NTOK*DI];
__device__ float g_pp[2*NTOK*DM];
__device__ float g_mask[NTOK];
__device__ float g_pooled[BATCH*DM];
__device__ int   g_eidx[NTOK];
__device__ float g_ew  [NTOK];
__device__ int   g_perm[NTOK];
__device__ int   g_cnt[NEXP], g_off[NEXP], g_fill[NEXP], g_cntb[BATCH];

// fp16 hi/lo split buffers (activations only)
__device__ __half g_xh[NTOK*DM],  g_xl[NTOK*DM];
__device__ __half g_uh[NTOK*DI],  g_ul[NTOK*DI];
__device__ __half g_yh[NTOK*DI],  g_yl[NTOK*DI];
__device__ __half g_hh[NTOK*HEXP],g_hl[NTOK*HEXP];
__device__ __half g_dah[NTOK*DTR],g_dal[NTOK*DTR];

// ---------------- PTX helpers (base ISA only) ----------------
__device__ __forceinline__ uint32_t smem_u32(const void* p) {
    uint32_t a;
    asm("{ .reg .u64 t; cvta.to.shared.u64 t, %1; cvt.u32.u64 %0, t; }" : "=r"(a) : "l"(p));
    return a;
}
__device__ __forceinline__ void ldsm4(uint32_t* r, uint32_t addr) {
    asm volatile("ldmatrix.sync.aligned.m8n8.x4.shared.b16 {%0,%1,%2,%3}, [%4];"
        : "=r"(r[0]), "=r"(r[1]), "=r"(r[2]), "=r"(r[3]) : "r"(addr));
}
__device__ __forceinline__ void mma_f16(float* c, const uint32_t* a, uint32_t b0, uint32_t b1) {
    asm volatile("mma.sync.aligned.m16n8k16.row.col.f32.f16.f16.f32 "
        "{%0,%1,%2,%3}, {%4,%5,%6,%7}, {%8,%9}, {%0,%1,%2,%3};"
        : "+f"(c[0]), "+f"(c[1]), "+f"(c[2]), "+f"(c[3])
        : "r"(a[0]), "r"(a[1]), "r"(a[2]), "r"(a[3]), "r"(b0), "r"(b1));
}
__device__ __forceinline__ void cpa16(uint32_t saddr, const void* g, bool v) {
    int sz = v ? 16 : 0;
    asm volatile("cp.async.cg.shared.global [%0], [%1], 16, %2;"
        :: "r"(saddr), "l"(g), "r"(sz));
}
__device__ __forceinline__ void cpa16f(uint32_t saddr, const void* g) {
    asm volatile("cp.async.cg.shared.global [%0], [%1], 16;"
        :: "r"(saddr), "l"(g));
}
#define CP_COMMIT() asm volatile("cp.async.commit_group;" ::: "memory")
#define CP_WAIT1()  asm volatile("cp.async.wait_group 1;" ::: "memory")
#define CP_WAIT0()  asm volatile("cp.async.wait_group 0;" ::: "memory")

// smem geometry: K-chunk 32 fp16 = 64B/row, padded to 80B
#define ROWB   80
#define TILEB  10240
#define STAGEB 40960
#define SM_TOT 81920

// ============ fused-split fp16 mma.sync GEMM ============
// terms==3: Ah*Wh + Al*Wh + Ah*Wl.  terms==2: Ah*Wh + Al*Wh.
__global__ void __launch_bounds__(256, 2)
mma_gemm(const __half* __restrict__ Ah, const __half* __restrict__ Al, int lda,
         const float* __restrict__ W32, int ldw, size_t wz,
         float* __restrict__ C, int ldc, size_t czs,
         __half* __restrict__ Ch, __half* __restrict__ Cl,
         const float* __restrict__ bias, int bias_z,
         int M_fixed, const int* __restrict__ cntp, const int* __restrict__ offp,
         const int* __restrict__ perm, const float* __restrict__ rowscale,
         int mode, int N, int K, int nyb, int act, int terms)
{
    int e = blockIdx.z;
    int M = cntp ? cntp[e] : M_fixed;
    int base = offp ? offp[e] : 0;
    int yy = blockIdx.y;
    int ks = yy / nyb;
    int nb = yy - ks * nyb;
    int bx = blockIdx.x;

    // raster swizzle: 4-wide m-supertiles for L2 locality
    {
        int nbx = gridDim.x;
        if (nbx >= 4) {
            int lin = nb * nbx + bx;
            int sw = 4 * nyb;
            int stile = lin / sw;
            int rem = lin - stile * sw;
            int m_in = rem % 4;
            int n_in = rem / 4;
            int mb = stile * 4 + m_in;
            if (mb < nbx) { bx = mb; nb = n_in; }
        }
    }

    int m0 = bx * 128;
    if (m0 >= M) return;
    int n0 = nb * 128;

    extern __shared__ char smem[];
    uint32_t sb = smem_u32(smem);
    int tid = threadIdx.x;

    int sub = tid & 3;
    int r0 = tid >> 2;
    size_t aoff[2]; uint32_t avm = 0;
#pragma unroll
    for (int i = 0; i < 2; i++) {
        int mm = m0 + r0 + 64 * i;
        bool av = mm < M;
        if (av) avm |= 1u << i;
        int ar;
        if (mode == 1)      ar = av ? perm[base + mm] : 0;
        else if (mode == 2) ar = base + (av ? mm : 0);
        else                ar = av ? mm : 0;
        aoff[i] = (size_t)ar * lda + sub * 8 + (size_t)ks * K;
    }
    uint32_t srow0 = r0 * ROWB + sub * 16;
    uint32_t srow1 = (r0 + 64) * ROWB + sub * 16;

    int wrow_l = tid >> 1;
    int wn = n0 + wrow_l;
    if (wn >= N) wn = 0;
    int khalf = (tid & 1) * 16;
    const float* WE = W32 + (size_t)e * wz + (size_t)wn * ldw + khalf + (size_t)ks * K;
    uint32_t wsts = (uint32_t)wrow_l * ROWB + (tid & 1) * 32;

    const int NC = K / 32;
    float4 wr[4];

#define COPY_A(c, s) do { \
        int _k0 = (c) * 32; \
        uint32_t _sB = sb + (uint32_t)(s) * STAGEB; \
        cpa16(_sB + srow0,         Ah + aoff[0] + _k0, avm & 1); \
        cpa16(_sB + srow1,         Ah + aoff[1] + _k0, (avm >> 1) & 1); \
        cpa16(_sB + TILEB + srow0, Al + aoff[0] + _k0, avm & 1); \
        cpa16(_sB + TILEB + srow1, Al + aoff[1] + _k0, (avm >> 1) & 1); \
    } while (0)

#define W_LDG(c) do { \
        const float4* _wp = reinterpret_cast<const float4*>(WE + (size_t)(c) * 32); \
        wr[0] = _wp[0]; wr[1] = _wp[1]; wr[2] = _wp[2]; wr[3] = _wp[3]; \
    } while (0)

#define W_STS(s) do { \
        float _wv[16]; \
        *(float4*)&_wv[0] = wr[0]; *(float4*)&_wv[4] = wr[1]; \
        *(float4*)&_wv[8] = wr[2]; *(float4*)&_wv[12] = wr[3]; \
        __half _hh[16]; \
        _Pragma("unroll") \
        for (int _i = 0; _i < 16; _i++) _hh[_i] = __float2half_rn(_wv[_i]); \
        char* _wh = smem + (uint32_t)(s) * STAGEB + 2 * TILEB + wsts; \
        *(uint4*)(_wh)      = *(uint4*)&_hh[0]; \
        *(uint4*)(_wh + 16) = *(uint4*)&_hh[8]; \
        if (terms == 3) { \
            __half _hl[16]; \
            _Pragma("unroll") \
            for (int _i = 0; _i < 16; _i++) \
                _hl[_i] = __float2half_rn(_wv[_i] - __half2float(_hh[_i])); \
            char* _wl = smem + (uint32_t)(s) * STAGEB + 3 * TILEB + wsts; \
            *(uint4*)(_wl)      = *(uint4*)&_hl[0]; \
            *(uint4*)(_wl + 16) = *(uint4*)&_hl[8]; \
        } \
    } while (0)

    int lane = tid & 31;
    int wid = tid >> 5;
    int wm = (wid & 3) * 32;
    int wn2 = (wid >> 2) * 64;

    uint32_t aRB = (uint32_t)(wm + (lane & 7) + ((lane >> 3) & 1) * 8) * ROWB + ((lane >> 4) & 1) * 16;
    uint32_t bRB = (uint32_t)(wn2 + (lane & 7) + ((lane >> 4) & 1) * 8) * ROWB + ((lane >> 3) & 1) * 16;

    float acc[2][8][4] = {};

    COPY_A(0, 0); CP_COMMIT();
    W_LDG(0);

    for (int c = 0; c < NC; c++) {
        if (c + 1 < NC) { COPY_A(c + 1, (c + 1) & 1); CP_COMMIT(); }
        W_STS(c & 1);
        if (c + 1 < NC) CP_WAIT1(); else CP_WAIT0();
        __syncthreads();
        if (c + 1 < NC) W_LDG(c + 1);

        uint32_t AhB = sb + (uint32_t)(c & 1) * STAGEB;
        uint32_t AlB = AhB + TILEB;
        uint32_t WhB = AhB + 2 * TILEB;
        uint32_t WlB = AhB + 3 * TILEB;
#pragma unroll
        for (int st = 0; st < 2; st++) {
            uint32_t kB = st * 32;
            uint32_t ah[2][4], al[2][4], bb[4][4];
#pragma unroll
            for (int im = 0; im < 2; im++)
                ldsm4(ah[im], AhB + (uint32_t)(im * 16) * ROWB + aRB + kB);
#pragma unroll
            for (int g = 0; g < 4; g++)
                ldsm4(bb[g], WhB + (uint32_t)(g * 16) * ROWB + bRB + kB);
#pragma unroll
            for (int im = 0; im < 2; im++)
#pragma unroll
                for (int in = 0; in < 8; in++)
                    mma_f16(acc[im][in], ah[im], bb[in >> 1][(in & 1) * 2], bb[in >> 1][(in & 1) * 2 + 1]);
#pragma unroll
            for (int im = 0; im < 2; im++)
                ldsm4(al[im], AlB + (uint32_t)(im * 16) * ROWB + aRB + kB);
#pragma unroll
            for (int im = 0; im < 2; im++)
#pragma unroll
                for (int in = 0; in < 8; in++)
                    mma_f16(acc[im][in], al[im], bb[in >> 1][(in & 1) * 2], bb[in >> 1][(in & 1) * 2 + 1]);
            if (terms == 3) {
#pragma unroll
                for (int g = 0; g < 4; g++)
                    ldsm4(bb[g], WlB + (uint32_t)(g * 16) * ROWB + bRB + kB);
#pragma unroll
                for (int im = 0; im < 2; im++)
#pragma unroll
                    for (int in = 0; in < 8; in++)
                        mma_f16(acc[im][in], ah[im], bb[in >> 1][(in & 1) * 2], bb[in >> 1][(in & 1) * 2 + 1]);
            }
        }
        __syncthreads();
    }

    // ---- epilogue ----
    int lq = lane >> 2;
    int lr = lane & 3;
    const float* bp = (bias && ks == 0) ? (bias + (size_t)e * bias_z) : nullptr;
    float* Cz = C ? (C + (size_t)ks * czs) : C;
#pragma unroll
    for (int im = 0; im < 2; im++) {
#pragma unroll
        for (int r2 = 0; r2 < 2; r2++) {
            int m = m0 + wm + im * 16 + lq + r2 * 8;
            if (m >= M) continue;
            long crow; float scale = 1.f;
            if (mode == 2)      { crow = perm[base + m]; scale = rowscale[crow]; }
            else if (mode == 1) { crow = base + m; }
            else                { crow = m; }
#pragma unroll
            for (int in = 0; in < 8; in++) {
                int n = n0 + wn2 + in * 8 + lr * 2;
                if (n >= N) continue;
                float v0 = acc[im][in][r2 * 2 + 0];
                float v1 = acc[im][in][r2 * 2 + 1];
                if (bp) { v0 += bp[n]; v1 += bp[n + 1]; }
                if (act == 1) { v0 = fmaxf(v0, 0.f); v1 = fmaxf(v1, 0.f); }
                else if (act == 2) {
                    v0 = (v0 > 20.f) ? v0 : log1pf(__expf(v0));
                    v1 = (v1 > 20.f) ? v1 : log1pf(__expf(v1));
                }
                if (Ch) {
                    __half h0 = __float2half_rn(v0);
                    __half h1 = __float2half_rn(v1);
                    size_t o = (size_t)crow * ldc + n;
                    Ch[o] = h0;     Cl[o]     = __float2half_rn(v0 - __half2float(h0));
                    Ch[o + 1] = h1; Cl[o + 1] = __float2half_rn(v1 - __half2float(h1));
                } else {
                    size_t o = (size_t)crow * ldc + n;
                    Cz[o] = v0 * scale;
                    Cz[o + 1] = v1 * scale;
                }
            }
        }
    }
#undef COPY_A
#undef W_LDG
#undef W_STS
}

// ---------------- fp16 split helpers ----------------
__device__ __forceinline__ void split2(float v, __half& h, __half& l) {
    h = __float2half_rn(v);
    l = __float2half_rn(v - __half2float(h));
}

// fused split-K reduce for xp + dt-input conversion
__global__ void xp_reduce_dt_k() {
    int i = blockIdx.x * 256 + threadIdx.x;
    float s = 0.f;
#pragma unroll
    for (int j = 0; j < KSPL; j++) s += g_xps[(size_t)j * NTOK * XPD + i];
    g_xp[i] = s;
    int t = i / XPD, c = i - t * XPD;
    if (c < DTR) {
        int o = t * DTR + c;
        split2(s, g_dah[o], g_dal[o]);
    }
}

// ---------------- embed ----------------
__global__ void embed_k(const int* __restrict__ tok, const float* __restrict__ emb,
                        const float* __restrict__ pos) {
    int i = blockIdx.x * blockDim.x + threadIdx.x;
    int t = i / DM, d = i % DM;
    int l = t % LSEQ;
    float v = emb[(size_t)tok[t] * DM + d] + pos[l * DM + d];
    g_x[i] = v;
    split2(v, g_xh[i], g_xl[i]);
}

// ---------------- conv + silu ----------------
__global__ void conv_silu_k(const float* __restrict__ cw, const float* __restrict__ cb) {
    int i = blockIdx.x * 256 + threadIdx.x;
    if (i >= NTOK * DI) return;
    int t = i / DI, d = i % DI;
    int b = t / LSEQ, l = t % LSEQ;
    float acc = cb[d];
#pragma unroll
    for (int k = 0; k < 4; k++) {
        int ll = l - 3 + k;
        if (ll >= 0) acc += g_uz[(size_t)(b * LSEQ + ll) * (2 * DI) + d] * cw[d * 4 + k];
    }
    float v = acc / (1.f + __expf(-acc));
    g_u[i] = v;
    split2(v, g_uh[i], g_ul[i]);
}

// ---------------- A structure detection: A[n] == -(n+1)? ----------------
__device__ __forceinline__ bool load_A(const float* A_log, int d, float* A) {
    bool fast = true;
#pragma unroll
    for (int n = 0; n < DS; n++) {
        A[n] = -expf(A_log[d * DS + n]);
        fast = fast && (fabsf(A[n] + (float)(n + 1)) < 1e-4f);
    }
    return fast;
}

// ---------------- single-pass selective scan with cp.async staging ----------------
// grid (BATCH, DI/128), 128 threads. Chunk = 32 steps, double buffered.
// smem floats: U[2][32][128] DT[..] Z[..] B[2][32][16] C[2][32][16]
#define SC_CH   32
#define SC_NC   (LSEQ / SC_CH)
#define SC_U    0
#define SC_DT   8192
#define SC_Z    16384
#define SC_B    24576
#define SC_C    25600
#define SC_SMEM (26624 * 4)

__global__ void __launch_bounds__(128) ssm_scan_k(const float* __restrict__ A_log,
                                                  const float* __restrict__ Dp) {
    int b = blockIdx.x;
    int d0 = blockIdx.y * 128;
    int tid = threadIdx.x;
    int d = d0 + tid;

    float A[DS];
    bool fast = load_A(A_log, d, A);
    float Dv = Dp[d];
    float h[DS];
#pragma unroll
    for (int n = 0; n < DS; n++) h[n] = 0.f;

    extern __shared__ float smf[];
    uint32_t sbase = smem_u32(smf);

#define SC_ISSUE(c) do { \
        int _buf = (c) & 1; \
        int _tokb = b * LSEQ + (c) * SC_CH; \
        _Pragma("unroll") \
        for (int _j = 0; _j < 8; _j++) { \
            int _q = _j * 128 + tid; \
            int _s = _q >> 5, _qd = (_q & 31) * 4; \
            uint32_t _o = (uint32_t)(_buf * 4096 + _s * 128 + _qd) * 4; \
            cpa16f(sbase + (SC_U  * 4) + _o, g_u  + (size_t)(_tokb + _s) * DI + d0 + _qd); \
            cpa16f(sbase + (SC_DT * 4) + _o, g_dt + (size_t)(_tokb + _s) * DI + d0 + _qd); \
            cpa16f(sbase + (SC_Z  * 4) + _o, g_uz + (size_t)(_tokb + _s) * (2 * DI) + DI + d0 + _qd); \
        } \
        { int _s = tid >> 2, _qd = (tid & 3) * 4; \
          uint32_t _o = (uint32_t)(_buf * 512 + _s * 16 + _qd) * 4; \
          cpa16f(sbase + (SC_B * 4) + _o, g_xp + (size_t)(_tokb + _s) * XPD + DTR + _qd); \
          cpa16f(sbase + (SC_C * 4) + _o, g_xp + (size_t)(_tokb + _s) * XPD + DTR + DS + _qd); } \
        CP_COMMIT(); \
    } while (0)

    SC_ISSUE(0);
    for (int c = 0; c < SC_NC; c++) {
        if (c + 1 < SC_NC) SC_ISSUE(c + 1);
        if (c + 1 < SC_NC) CP_WAIT1(); else CP_WAIT0();
        __syncthreads();
        int buf = c & 1;
        int tokb = b * LSEQ + c * SC_CH;
        const float* su = smf + SC_U  + buf * 4096 + tid;
        const float* sd = smf + SC_DT + buf * 4096 + tid;
        const float* sz = smf + SC_Z  + buf * 4096 + tid;
        const float* sB = smf + SC_B + buf * 512;
        const float* sC = smf + SC_C + buf * 512;
        if (fast) {
            for (int s = 0; s < SC_CH; s++) {
                float ut  = su[s * 128];
                float dtt = sd[s * 128];
                float z   = sz[s * 128];
                float du = dtt * ut;
                // E powers via product tree (depth ~4, no 16-deep serial chain)
                float e1 = __expf(-dtt);
                float e2 = e1 * e1, e3 = e2 * e1, e4 = e2 * e2;
                float e8 = e4 * e4, e12 = e8 * e4;
                float pw[DS] = {e1, e2, e3, e4,
                                e4 * e1, e4 * e2, e4 * e3, e8,
                                e8 * e1, e8 * e2, e8 * e3, e12,
                                e12 * e1, e12 * e2, e12 * e3, e8 * e8};
                float yv = 0.f;
#pragma unroll
                for (int n = 0; n < DS; n++) {
                    h[n] = pw[n] * h[n] + du * sB[s * 16 + n];
                    yv += h[n] * sC[s * 16 + n];
                }
                yv += ut * Dv;
                float y = yv * (z / (1.f + __expf(-z)));
                size_t o = (size_t)(tokb + s) * DI + d;
                split2(y, g_yh[o], g_yl[o]);
            }
        } else {
            for (int s = 0; s < SC_CH; s++) {
                float ut  = su[s * 128];
                float dtt = sd[s * 128];
                float z   = sz[s * 128];
                float du = dtt * ut;
                float yv = 0.f;
#pragma unroll
                for (int n = 0; n < DS; n++) {
                    h[n] = __expf(dtt * A[n]) * h[n] + du * sB[s * 16 + n];
                    yv += h[n] * sC[s * 16 + n];
                }
                yv += ut * Dv;
                float y = yv * (z / (1.f + __expf(-z)));
                size_t o = (size_t)(tokb + s) * DI + d;
                split2(y, g_yh[o], g_yl[o]);
            }
        }
        __syncthreads();
    }
#undef SC_ISSUE
}

// ---------------- x += LayerNorm(t0 + t1); optional fused MoE gate ----------------
__global__ void addln_k(const float* __restrict__ g, const float* __restrict__ bb,
                        const float* __restrict__ t0, const float* __restrict__ t1,
                        const float* __restrict__ gw, const float* __restrict__ gb,
                        int cntb_rst) {
    int tok = blockIdx.x;
    int tid = threadIdx.x;
    if (gw && tok == 0 && tid < NEXP) { g_cnt[tid] = 0; g_fill[tid] = 0; }
    if (cntb_rst && tok == 0 && tid < BATCH) g_cntb[tid] = 0;
    float* x = g_x + (size_t)tok * DM;
    float v[4]; float s = 0.f;
#pragma unroll
    for (int i = 0; i < 4; i++) {
        size_t o = (size_t)tok * DM + tid + i * 256;
        v[i] = t0[o] + t1[o];
        s += v[i];
    }
    __shared__ float sm[256];
    sm[tid] = s; __syncthreads();
    for (int st = 128; st > 0; st >>= 1) { if (tid < st) sm[tid] += sm[tid + st]; __syncthreads(); }
    float mean = sm[0] / DM;
    __syncthreads();
    float q = 0.f;
#pragma unroll
    for (int i = 0; i < 4; i++) { float dd = v[i] - mean; q += dd * dd; }
    sm[tid] = q; __syncthreads();
    for (int st = 128; st > 0; st >>= 1) { if (tid < st) sm[tid] += sm[tid + st]; __syncthreads(); }
    float rstd = rsqrtf(sm[0] / DM + 1e-5f);

    float nx[4];
#pragma unroll
    for (int i = 0; i < 4; i++) {
        int d = tid + i * 256;
        nx[i] = x[d] + (v[i] - mean) * rstd * g[d] + bb[d];
        x[d] = nx[i];
        split2(nx[i], g_xh[(size_t)tok * DM + d], g_xl[(size_t)tok * DM + d]);
    }

    if (gw) {
        __shared__ float gsm[NEXP][256];
        float p[NEXP];
#pragma unroll
        for (int e = 0; e < NEXP; e++) p[e] = 0.f;
#pragma unroll
        for (int i = 0; i < 4; i++) {
            int d = tid + i * 256;
            float xv = nx[i];
#pragma unroll
            for (int e = 0; e < NEXP; e++) p[e] += xv * gw[e * DM + d];
        }
        __syncthreads();
#pragma unroll
        for (int e = 0; e < NEXP; e++) gsm[e][tid] = p[e];
        __syncthreads();
        for (int st = 128; st > 0; st >>= 1) {
            if (tid < st)
#pragma unroll
                for (int e = 0; e < NEXP; e++) gsm[e][tid] += gsm[e][tid + st];
            __syncthreads();
        }
        if (tid == 0) {
            float m = -1e30f; int bi = 0;
            float lg[NEXP];
#pragma unroll
            for (int e = 0; e < NEXP; e++) {
                lg[e] = gsm[e][0] + gb[e];
                if (lg[e] > m) { m = lg[e]; bi = e; }
            }
            float ssum = 0.f;
#pragma unroll
            for (int e = 0; e < NEXP; e++) ssum += __expf(lg[e] - m);
            g_eidx[tok] = bi;
            g_ew[tok] = 1.f / ssum;
            atomicAdd(&g_cnt[bi], 1);
        }
    }
}

// ---------------- moe1 combine ----------------
__global__ void moe1_comb(const float* __restrict__ b1) {
    int i = blockIdx.x * 256 + threadIdx.x;
    int r = i >> 10, col = i & 1023;
    int e = g_eidx[g_perm[r]];
    float v = g_pp[i] + g_pp[NTOK * HEXP + i] + b1[e * HEXP + col];
    v = fmaxf(v, 0.f);
    split2(v, g_hh[i], g_hl[i]);
}

__global__ void route_offsets_k() {
    if (threadIdx.x == 0) { int o = 0; for (int e = 0; e < NEXP; e++) { g_off[e] = o; o += g_cnt[e]; } }
}
__global__ void route_scatter_k() {
    int tok = blockIdx.x * 256 + threadIdx.x;
    if (tok < NTOK) {
        int e = g_eidx[tok];
        int p = g_off[e] + atomicAdd(&g_fill[e], 1);
        g_perm[p] = tok;
    }
}

// ---------------- pooling + head ----------------
__global__ void rowmask_k() {
    int tok = blockIdx.x;
    int tid = threadIdx.x;
    float s = 0.f;
#pragma unroll
    for (int i = 0; i < 4; i++) s += g_x[(size_t)tok * DM + tid + i * 256];
    __shared__ float sm[256];
    sm[tid] = s; __syncthreads();
    for (int st = 128; st > 0; st >>= 1) { if (tid < st) sm[tid] += sm[tid + st]; __syncthreads(); }
    if (tid == 0) {
        float m = (sm[0] != 0.f) ? 1.f : 0.f;
        g_mask[tok] = m;
        if (m != 0.f) atomicAdd(&g_cntb[tok / LSEQ], 1);
    }
}

__global__ void pool_k() {
    int b = blockIdx.x;
    int d = blockIdx.y * 256 + threadIdx.x;
    float acc = 0.f;
    for (int l = 0; l < LSEQ; l++)
        acc += g_x[(size_t)(b * LSEQ + l) * DM + d] * g_mask[b * LSEQ + l];
    g_pooled[b * DM + d] = acc / fmaxf((float)g_cntb[b], 1.f);
}

__global__ void head_k(const float* __restrict__ w1, const float* __restrict__ b1,
                       const float* __restrict__ w2, const float* __restrict__ b2,
                       float* __restrict__ out) {
    int b = blockIdx.x;
    int j = threadIdx.x;
    const float* p = g_pooled + b * DM;
    float acc = b1[j];
    for (int k = 0; k < DM; k++) acc += p[k] * w1[j * DM + k];
    __shared__ float h[128];
    h[j] = fmaxf(acc, 0.f);
    __syncthreads();
    if (j < 2) {
        float o = b2[j];
        for (int k = 0; k < 128; k++) o += h[k] * w2[j * 128 + k];
        out[b * 2 + j] = o;
    }
}

// ---------------- launch ----------------
extern "C" void kernel_launch(void* const* d_in, const int* in_sizes, int n_in,
                              void* d_out, int out_size) {
    const int*   tok    = (const int*)  d_in[0];
    const float* emb    = (const float*)d_in[1];
    const float* pos    = (const float*)d_in[2];
    const float* in_w   = (const float*)d_in[3];
    const float* conv_w = (const float*)d_in[4];
    const float* conv_b = (const float*)d_in[5];
    const float* xp_w   = (const float*)d_in[6];
    const float* dt_w   = (const float*)d_in[7];
    const float* dt_b   = (const float*)d_in[8];
    const float* A_log  = (const float*)d_in[9];
    const float* D_ssm  = (const float*)d_in[10];
    const float* out_w  = (const float*)d_in[11];
    const float* ln1_g  = (const float*)d_in[12];
    const float* ln1_b  = (const float*)d_in[13];
    const float* ln2_g  = (const float*)d_in[14];
    const float* ln2_b  = (const float*)d_in[15];
    const float* gate_w = (const float*)d_in[16];
    const float* gate_b = (const float*)d_in[17];
    const float* e_w1   = (const float*)d_in[18];
    const float* e_b1   = (const float*)d_in[19];
    const float* e_w2   = (const float*)d_in[20];
    const float* e_b2   = (const float*)d_in[21];
    const float* fc1_w  = (const float*)d_in[22];
    const float* fc1_b  = (const float*)d_in[23];
    const float* fc2_w  = (const float*)d_in[24];
    const float* fc2_b  = (const float*)d_in[25];
    float* out = (float*)d_out;

    cudaFuncSetAttribute(mma_gemm, cudaFuncAttributeMaxDynamicSharedMemorySize, SM_TOT);
    cudaFuncSetAttribute(ssm_scan_k, cudaFuncAttributeMaxDynamicSharedMemorySize, SC_SMEM);

    float *puz, *pxps, *pdt, *ppp, *pew;
    __half *pxh, *pxl, *puh, *pul, *pyh, *pyl, *phh, *phl, *pdah, *pdal;
    int *pcnt, *poff, *pperm;
    cudaGetSymbolAddress((void**)&puz,  g_uz);
    cudaGetSymbolAddress((void**)&pxps, g_xps);
    cudaGetSymbolAddress((void**)&pdt,  g_dt);
    cudaGetSymbolAddress((void**)&ppp,  g_pp);
    cudaGetSymbolAddress((void**)&pew,  g_ew);
    cudaGetSymbolAddress((void**)&pxh,  g_xh);
    cudaGetSymbolAddress((void**)&pxl,  g_xl);
    cudaGetSymbolAddress((void**)&puh,  g_uh);
    cudaGetSymbolAddress((void**)&pul,  g_ul);
    cudaGetSymbolAddress((void**)&pyh,  g_yh);
    cudaGetSymbolAddress((void**)&pyl,  g_yl);
    cudaGetSymbolAddress((void**)&phh,  g_hh);
    cudaGetSymbolAddress((void**)&phl,  g_hl);
    cudaGetSymbolAddress((void**)&pdah, g_dah);
    cudaGetSymbolAddress((void**)&pdal, g_dal);
    cudaGetSymbolAddress((void**)&pcnt, g_cnt);
    cudaGetSymbolAddress((void**)&poff, g_off);
    cudaGetSymbolAddress((void**)&pperm,g_perm);

    embed_k<<<(NTOK * DM) / 256, 256>>>(tok, emb, pos);

    for (int l = 0; l < 2; l++) {
        const float* in_w_l  = in_w  + (size_t)l * 2 * DI * DM;
        const float* xp_w_l  = xp_w  + (size_t)l * XPD * DI;
        const float* dt_w_l  = dt_w  + (size_t)l * DI * DTR;
        const float* out_w_l = out_w + (size_t)l * DM * DI;
        const float* e_w1_l  = e_w1  + (size_t)l * NEXP * HEXP * DM;
        const float* e_w2_l  = e_w2  + (size_t)l * NEXP * DM * HEXP;
        const float* A_log_l = A_log + (size_t)l * DI * DS;
        int t2 = (l == 1) ? 2 : 3;

        // in_proj (3-term: feeds the scan path)
        mma_gemm<<<dim3(32, 32, 1), 256, SM_TOT>>>(
            pxh, pxl, DM, in_w_l, DM, 0, puz, 2 * DI, 0, nullptr, nullptr,
            nullptr, 0, NTOK, nullptr, nullptr, nullptr, nullptr, 0, 2 * DI, DM, 32, 0, 3);

        conv_silu_k<<<(NTOK * DI) / 256, 256>>>(conv_w + (size_t)l * DI * 4, conv_b + (size_t)l * DI);

        // xp: split-K x8 (3-term)
        mma_gemm<<<dim3(32, KSPL, 1), 256, SM_TOT>>>(
            puh, pul, DI, xp_w_l, DI, 0, pxps, XPD, (size_t)NTOK * XPD, nullptr, nullptr,
            nullptr, 0, NTOK, nullptr, nullptr, nullptr, nullptr, 0, XPD, DI / KSPL, 1, 0, 3);
        xp_reduce_dt_k<<<(NTOK * XPD) / 256, 256>>>();

        // dt (3-term)
        mma_gemm<<<dim3(32, 16, 1), 256, SM_TOT>>>(
            pdah, pdal, DTR, dt_w_l, DTR, 0, pdt, DI, 0, nullptr, nullptr,
            dt_b + (size_t)l * DI, 0, NTOK, nullptr, nullptr, nullptr, nullptr, 0, DI, DTR, 16, 2, 3);

        // single-pass scan (cp.async staged, fast-A powers)
        ssm_scan_k<<<dim3(BATCH, DI / 128), 128, SC_SMEM>>>(
            A_log_l, D_ssm + (size_t)l * DI);

        // out: split-K x2
        mma_gemm<<<dim3(32, 16, 1), 256, SM_TOT>>>(
            pyh, pyl, DI, out_w_l, DI, 0, ppp, DM, (size_t)NTOK * DM, nullptr, nullptr,
            nullptr, 0, NTOK, nullptr, nullptr, nullptr, nullptr, 0, DM, DI / 2, 8, 0, t2);

        // x += LN(out) with fused gate
        addln_k<<<NTOK, 256>>>(ln1_g + (size_t)l * DM, ln1_b + (size_t)l * DM,
                               ppp, ppp + (size_t)NTOK * DM,
                               gate_w + (size_t)l * NEXP * DM, gate_b + (size_t)l * NEXP, 0);

        route_offsets_k<<<1, 1>>>();
        route_scatter_k<<<NTOK / 256, 256>>>();

        // moe1: split-K x2 + combine
        mma_gemm<<<dim3(32, 16, NEXP), 256, SM_TOT>>>(
            pxh, pxl, DM, e_w1_l, DM, (size_t)HEXP * DM, ppp, HEXP, (size_t)NTOK * HEXP,
            nullptr, nullptr, nullptr, 0, 0, pcnt, poff, pperm, nullptr, 1, HEXP, DM / 2, 8, 0, t2);
        moe1_comb<<<(NTOK * HEXP) / 256, 256>>>(e_b1 + (size_t)l * NEXP * HEXP);

        // moe2: split-K x2
        mma_gemm<<<dim3(32, 16, NEXP), 256, SM_TOT>>>(
            phh, phl, HEXP, e_w2_l, HEXP, (size_t)DM * HEXP, ppp, DM, (size_t)NTOK * DM,
            nullptr, nullptr, e_b2 + (size_t)l * NEXP * DM, DM, 0, pcnt, poff, pperm, pew,
            2, DM, HEXP / 2, 8, 0, t2);

        addln_k<<<NTOK, 256>>>(ln2_g + (size_t)l * DM, ln2_b + (size_t)l * DM,
                               ppp, ppp + (size_t)NTOK * DM, nullptr, nullptr, (l == 1) ? 1 : 0);
    }

    rowmask_k<<<NTOK, 256>>>();
    pool_k<<<dim3(BATCH, DM / 256), 256>>>();
    head_k<<<BATCH, 128>>>(fc1_w, fc1_b, fc2_w, fc2_b, out);
}

// round 15
// speedup vs baseline: 1.0136x; 1.0136x over previous
#include <cuda_runtime.h>
#include <cuda_fp16.h>
#include <math.h>
#include <stdint.h>

// ---------------- problem constants ----------------
#define NTOK  4096
#define LSEQ  1024
#define BATCH 4
#define DM    1024
#define DI    2048
#define DS    16
#define DTR   64
#define XPD   96
#define NEXP  8
#define HEXP  1024
#define KSPL  8

// ---------------- device scratch ----------------
__device__ float g_x [NTOK*DM];
__device__ float g_uz[NTOK*2*DI];
__device__ float g_u [NTOK*DI];
__device__ float g_xp[NTOK*XPD];
__device__ float g_xps[KSPL*NTOK*XPD];
__device__ float g_dt[NTOK*DI];
__device__ float g_pp[2*NTOK*DM];
__device__ float g_mask[NTOK];
__device__ float g_pooled[BATCH*DM];
__device__ int   g_eidx[NTOK];
__device__ float g_ew  [NTOK];
__device__ int   g_perm[NTOK];
__device__ int   g_cnt[NEXP], g_off[NEXP], g_fill[NEXP], g_cntb[BATCH];

// fp16 hi/lo split buffers (activations only)
__device__ __half g_xh[NTOK*DM],  g_xl[NTOK*DM];
__device__ __half g_uh[NTOK*DI],  g_ul[NTOK*DI];
__device__ __half g_yh[NTOK*DI],  g_yl[NTOK*DI];
__device__ __half g_hh[NTOK*HEXP],g_hl[NTOK*HEXP];
__device__ __half g_dah[NTOK*DTR],g_dal[NTOK*DTR];

// ---------------- PTX helpers (base ISA only) ----------------
__device__ __forceinline__ uint32_t smem_u32(const void* p) {
    uint32_t a;
    asm("{ .reg .u64 t; cvta.to.shared.u64 t, %1; cvt.u32.u64 %0, t; }" : "=r"(a) : "l"(p));
    return a;
}
__device__ __forceinline__ void ldsm4(uint32_t* r, uint32_t addr) {
    asm volatile("ldmatrix.sync.aligned.m8n8.x4.shared.b16 {%0,%1,%2,%3}, [%4];"
        : "=r"(r[0]), "=r"(r[1]), "=r"(r[2]), "=r"(r[3]) : "r"(addr));
}
__device__ __forceinline__ void mma_f16(float* c, const uint32_t* a, uint32_t b0, uint32_t b1) {
    asm volatile("mma.sync.aligned.m16n8k16.row.col.f32.f16.f16.f32 "
        "{%0,%1,%2,%3}, {%4,%5,%6,%7}, {%8,%9}, {%0,%1,%2,%3};"
        : "+f"(c[0]), "+f"(c[1]), "+f"(c[2]), "+f"(c[3])
        : "r"(a[0]), "r"(a[1]), "r"(a[2]), "r"(a[3]), "r"(b0), "r"(b1));
}
__device__ __forceinline__ void cpa16(uint32_t saddr, const void* g, bool v) {
    int sz = v ? 16 : 0;
    asm volatile("cp.async.cg.shared.global [%0], [%1], 16, %2;"
        :: "r"(saddr), "l"(g), "r"(sz));
}
__device__ __forceinline__ void cpa16f(uint32_t saddr, const void* g) {
    asm volatile("cp.async.cg.shared.global [%0], [%1], 16;"
        :: "r"(saddr), "l"(g));
}
#define CP_COMMIT() asm volatile("cp.async.commit_group;" ::: "memory")
#define CP_WAIT1()  asm volatile("cp.async.wait_group 1;" ::: "memory")
#define CP_WAIT0()  asm volatile("cp.async.wait_group 0;" ::: "memory")

// smem geometry: K-chunk 32 fp16 = 64B/row, padded to 80B
#define ROWB   80
#define TILEB  10240
#define STAGEB 40960
#define SM_TOT 81920

// ============ fused-split fp16 mma.sync GEMM ============
// terms==3: Ah*Wh + Al*Wh + Ah*Wl (3rd term only for n0 < t3lim).  terms==2: Ah*Wh + Al*Wh.
__global__ void __launch_bounds__(256, 2)
mma_gemm(const __half* __restrict__ Ah, const __half* __restrict__ Al, int lda,
         const float* __restrict__ W32, int ldw, size_t wz,
         float* __restrict__ C, int ldc, size_t czs,
         __half* __restrict__ Ch, __half* __restrict__ Cl,
         const float* __restrict__ bias, int bias_z,
         int M_fixed, const int* __restrict__ cntp, const int* __restrict__ offp,
         const int* __restrict__ perm, const float* __restrict__ rowscale,
         int mode, int N, int K, int nyb, int act, int terms, int t3lim)
{
    int e = blockIdx.z;
    int M = cntp ? cntp[e] : M_fixed;
    int base = offp ? offp[e] : 0;
    int yy = blockIdx.y;
    int ks = yy / nyb;
    int nb = yy - ks * nyb;
    int bx = blockIdx.x;

    // raster swizzle: 4-wide m-supertiles for L2 locality
    {
        int nbx = gridDim.x;
        if (nbx >= 4) {
            int lin = nb * nbx + bx;
            int sw = 4 * nyb;
            int stile = lin / sw;
            int rem = lin - stile * sw;
            int m_in = rem % 4;
            int n_in = rem / 4;
            int mb = stile * 4 + m_in;
            if (mb < nbx) { bx = mb; nb = n_in; }
        }
    }

    int m0 = bx * 128;
    if (m0 >= M) return;
    int n0 = nb * 128;
    int use3 = (terms == 3) && (n0 < t3lim);

    extern __shared__ char smem[];
    uint32_t sb = smem_u32(smem);
    int tid = threadIdx.x;

    int sub = tid & 3;
    int r0 = tid >> 2;
    size_t aoff[2]; uint32_t avm = 0;
#pragma unroll
    for (int i = 0; i < 2; i++) {
        int mm = m0 + r0 + 64 * i;
        bool av = mm < M;
        if (av) avm |= 1u << i;
        int ar;
        if (mode == 1)      ar = av ? perm[base + mm] : 0;
        else if (mode == 2) ar = base + (av ? mm : 0);
        else                ar = av ? mm : 0;
        aoff[i] = (size_t)ar * lda + sub * 8 + (size_t)ks * K;
    }
    uint32_t srow0 = r0 * ROWB + sub * 16;
    uint32_t srow1 = (r0 + 64) * ROWB + sub * 16;

    int wrow_l = tid >> 1;
    int wn = n0 + wrow_l;
    if (wn >= N) wn = 0;
    int khalf = (tid & 1) * 16;
    const float* WE = W32 + (size_t)e * wz + (size_t)wn * ldw + khalf + (size_t)ks * K;
    uint32_t wsts = (uint32_t)wrow_l * ROWB + (tid & 1) * 32;

    const int NC = K / 32;
    float4 wr[4];

#define COPY_A(c, s) do { \
        int _k0 = (c) * 32; \
        uint32_t _sB = sb + (uint32_t)(s) * STAGEB; \
        cpa16(_sB + srow0,         Ah + aoff[0] + _k0, avm & 1); \
        cpa16(_sB + srow1,         Ah + aoff[1] + _k0, (avm >> 1) & 1); \
        cpa16(_sB + TILEB + srow0, Al + aoff[0] + _k0, avm & 1); \
        cpa16(_sB + TILEB + srow1, Al + aoff[1] + _k0, (avm >> 1) & 1); \
    } while (0)

#define W_LDG(c) do { \
        const float4* _wp = reinterpret_cast<const float4*>(WE + (size_t)(c) * 32); \
        wr[0] = _wp[0]; wr[1] = _wp[1]; wr[2] = _wp[2]; wr[3] = _wp[3]; \
    } while (0)

#define W_STS(s) do { \
        float _wv[16]; \
        *(float4*)&_wv[0] = wr[0]; *(float4*)&_wv[4] = wr[1]; \
        *(float4*)&_wv[8] = wr[2]; *(float4*)&_wv[12] = wr[3]; \
        __half _hh[16]; \
        _Pragma("unroll") \
        for (int _i = 0; _i < 16; _i++) _hh[_i] = __float2half_rn(_wv[_i]); \
        char* _wh = smem + (uint32_t)(s) * STAGEB + 2 * TILEB + wsts; \
        *(uint4*)(_wh)      = *(uint4*)&_hh[0]; \
        *(uint4*)(_wh + 16) = *(uint4*)&_hh[8]; \
        if (use3) { \
            __half _hl[16]; \
            _Pragma("unroll") \
            for (int _i = 0; _i < 16; _i++) \
                _hl[_i] = __float2half_rn(_wv[_i] - __half2float(_hh[_i])); \
            char* _wl = smem + (uint32_t)(s) * STAGEB + 3 * TILEB + wsts; \
            *(uint4*)(_wl)      = *(uint4*)&_hl[0]; \
            *(uint4*)(_wl + 16) = *(uint4*)&_hl[8]; \
        } \
    } while (0)

    int lane = tid & 31;
    int wid = tid >> 5;
    int wm = (wid & 3) * 32;
    int wn2 = (wid >> 2) * 64;

    uint32_t aRB = (uint32_t)(wm + (lane & 7) + ((lane >> 3) & 1) * 8) * ROWB + ((lane >> 4) & 1) * 16;
    uint32_t bRB = (uint32_t)(wn2 + (lane & 7) + ((lane >> 4) & 1) * 8) * ROWB + ((lane >> 3) & 1) * 16;

    float acc[2][8][4] = {};

    COPY_A(0, 0); CP_COMMIT();
    W_LDG(0);

    for (int c = 0; c < NC; c++) {
        if (c + 1 < NC) { COPY_A(c + 1, (c + 1) & 1); CP_COMMIT(); }
        W_STS(c & 1);
        if (c + 1 < NC) CP_WAIT1(); else CP_WAIT0();
        __syncthreads();
        if (c + 1 < NC) W_LDG(c + 1);

        uint32_t AhB = sb + (uint32_t)(c & 1) * STAGEB;
        uint32_t AlB = AhB + TILEB;
        uint32_t WhB = AhB + 2 * TILEB;
        uint32_t WlB = AhB + 3 * TILEB;
#pragma unroll
        for (int st = 0; st < 2; st++) {
            uint32_t kB = st * 32;
            uint32_t ah[2][4], al[2][4], bb[4][4];
#pragma unroll
            for (int im = 0; im < 2; im++)
                ldsm4(ah[im], AhB + (uint32_t)(im * 16) * ROWB + aRB + kB);
#pragma unroll
            for (int g = 0; g < 4; g++)
                ldsm4(bb[g], WhB + (uint32_t)(g * 16) * ROWB + bRB + kB);
#pragma unroll
            for (int im = 0; im < 2; im++)
#pragma unroll
                for (int in = 0; in < 8; in++)
                    mma_f16(acc[im][in], ah[im], bb[in >> 1][(in & 1) * 2], bb[in >> 1][(in & 1) * 2 + 1]);
#pragma unroll
            for (int im = 0; im < 2; im++)
                ldsm4(al[im], AlB + (uint32_t)(im * 16) * ROWB + aRB + kB);
#pragma unroll
            for (int im = 0; im < 2; im++)
#pragma unroll
                for (int in = 0; in < 8; in++)
                    mma_f16(acc[im][in], al[im], bb[in >> 1][(in & 1) * 2], bb[in >> 1][(in & 1) * 2 + 1]);
            if (use3) {
#pragma unroll
                for (int g = 0; g < 4; g++)
                    ldsm4(bb[g], WlB + (uint32_t)(g * 16) * ROWB + bRB + kB);
#pragma unroll
                for (int im = 0; im < 2; im++)
#pragma unroll
                    for (int in = 0; in < 8; in++)
                        mma_f16(acc[im][in], ah[im], bb[in >> 1][(in & 1) * 2], bb[in >> 1][(in & 1) * 2 + 1]);
            }
        }
        __syncthreads();
    }

    // ---- epilogue ----
    int lq = lane >> 2;
    int lr = lane & 3;
    const float* bp = (bias && ks == 0) ? (bias + (size_t)e * bias_z) : nullptr;
    float* Cz = C ? (C + (size_t)ks * czs) : C;
#pragma unroll
    for (int im = 0; im < 2; im++) {
#pragma unroll
        for (int r2 = 0; r2 < 2; r2++) {
            int m = m0 + wm + im * 16 + lq + r2 * 8;
            if (m >= M) continue;
            long crow; float scale = 1.f;
            if (mode == 2)      { crow = perm[base + m]; scale = rowscale[crow]; }
            else if (mode == 1) { crow = base + m; }
            else                { crow = m; }
#pragma unroll
            for (int in = 0; in < 8; in++) {
                int n = n0 + wn2 + in * 8 + lr * 2;
                if (n >= N) continue;
                float v0 = acc[im][in][r2 * 2 + 0];
                float v1 = acc[im][in][r2 * 2 + 1];
                if (bp) { v0 += bp[n]; v1 += bp[n + 1]; }
                if (act == 1) { v0 = fmaxf(v0, 0.f); v1 = fmaxf(v1, 0.f); }
                else if (act == 2) {
                    v0 = (v0 > 20.f) ? v0 : log1pf(__expf(v0));
                    v1 = (v1 > 20.f) ? v1 : log1pf(__expf(v1));
                }
                if (Ch) {
                    __half h0 = __float2half_rn(v0);
                    __half h1 = __float2half_rn(v1);
                    size_t o = (size_t)crow * ldc + n;
                    Ch[o] = h0;     Cl[o]     = __float2half_rn(v0 - __half2float(h0));
                    Ch[o + 1] = h1; Cl[o + 1] = __float2half_rn(v1 - __half2float(h1));
                } else {
                    size_t o = (size_t)crow * ldc + n;
                    Cz[o] = v0 * scale;
                    Cz[o + 1] = v1 * scale;
                }
            }
        }
    }
#undef COPY_A
#undef W_LDG
#undef W_STS
}

// ---------------- fp16 split helpers ----------------
__device__ __forceinline__ void split2(float v, __half& h, __half& l) {
    h = __float2half_rn(v);
    l = __float2half_rn(v - __half2float(h));
}

// fused split-K reduce for xp + dt-input conversion
__global__ void xp_reduce_dt_k() {
    int i = blockIdx.x * 256 + threadIdx.x;
    float s = 0.f;
#pragma unroll
    for (int j = 0; j < KSPL; j++) s += g_xps[(size_t)j * NTOK * XPD + i];
    g_xp[i] = s;
    int t = i / XPD, c = i - t * XPD;
    if (c < DTR) {
        int o = t * DTR + c;
        split2(s, g_dah[o], g_dal[o]);
    }
}

// ---------------- embed ----------------
__global__ void embed_k(const int* __restrict__ tok, const float* __restrict__ emb,
                        const float* __restrict__ pos) {
    int i = blockIdx.x * blockDim.x + threadIdx.x;
    int t = i / DM, d = i % DM;
    int l = t % LSEQ;
    float v = emb[(size_t)tok[t] * DM + d] + pos[l * DM + d];
    g_x[i] = v;
    split2(v, g_xh[i], g_xl[i]);
}

// ---------------- conv + silu ----------------
__global__ void conv_silu_k(const float* __restrict__ cw, const float* __restrict__ cb) {
    int i = blockIdx.x * 256 + threadIdx.x;
    if (i >= NTOK * DI) return;
    int t = i / DI, d = i % DI;
    int b = t / LSEQ, l = t % LSEQ;
    float acc = cb[d];
#pragma unroll
    for (int k = 0; k < 4; k++) {
        int ll = l - 3 + k;
        if (ll >= 0) acc += g_uz[(size_t)(b * LSEQ + ll) * (2 * DI) + d] * cw[d * 4 + k];
    }
    float v = acc / (1.f + __expf(-acc));
    g_u[i] = v;
    split2(v, g_uh[i], g_ul[i]);
}

// ---------------- A structure detection: A[n] == -(n+1)? ----------------
__device__ __forceinline__ bool load_A(const float* A_log, int d, float* A) {
    bool fast = true;
#pragma unroll
    for (int n = 0; n < DS; n++) {
        A[n] = -expf(A_log[d * DS + n]);
        fast = fast && (fabsf(A[n] + (float)(n + 1)) < 1e-4f);
    }
    return fast;
}

// ---------------- single-pass selective scan with cp.async staging ----------------
#define SC_CH   32
#define SC_NC   (LSEQ / SC_CH)
#define SC_U    0
#define SC_DT   8192
#define SC_Z    16384
#define SC_B    24576
#define SC_C    25600
#define SC_SMEM (26624 * 4)

__global__ void __launch_bounds__(128) ssm_scan_k(const float* __restrict__ A_log,
                                                  const float* __restrict__ Dp) {
    int b = blockIdx.x;
    int d0 = blockIdx.y * 128;
    int tid = threadIdx.x;
    int d = d0 + tid;

    float A[DS];
    bool fast = load_A(A_log, d, A);
    float Dv = Dp[d];
    float h[DS];
#pragma unroll
    for (int n = 0; n < DS; n++) h[n] = 0.f;

    extern __shared__ float smf[];
    uint32_t sbase = smem_u32(smf);

#define SC_ISSUE(c) do { \
        int _buf = (c) & 1; \
        int _tokb = b * LSEQ + (c) * SC_CH; \
        _Pragma("unroll") \
        for (int _j = 0; _j < 8; _j++) { \
            int _q = _j * 128 + tid; \
            int _s = _q >> 5, _qd = (_q & 31) * 4; \
            uint32_t _o = (uint32_t)(_buf * 4096 + _s * 128 + _qd) * 4; \
            cpa16f(sbase + (SC_U  * 4) + _o, g_u  + (size_t)(_tokb + _s) * DI + d0 + _qd); \
            cpa16f(sbase + (SC_DT * 4) + _o, g_dt + (size_t)(_tokb + _s) * DI + d0 + _qd); \
            cpa16f(sbase + (SC_Z  * 4) + _o, g_uz + (size_t)(_tokb + _s) * (2 * DI) + DI + d0 + _qd); \
        } \
        { int _s = tid >> 2, _qd = (tid & 3) * 4; \
          uint32_t _o = (uint32_t)(_buf * 512 + _s * 16 + _qd) * 4; \
          cpa16f(sbase + (SC_B * 4) + _o, g_xp + (size_t)(_tokb + _s) * XPD + DTR + _qd); \
          cpa16f(sbase + (SC_C * 4) + _o, g_xp + (size_t)(_tokb + _s) * XPD + DTR + DS + _qd); } \
        CP_COMMIT(); \
    } while (0)

    SC_ISSUE(0);
    for (int c = 0; c < SC_NC; c++) {
        if (c + 1 < SC_NC) SC_ISSUE(c + 1);
        if (c + 1 < SC_NC) CP_WAIT1(); else CP_WAIT0();
        __syncthreads();
        int buf = c & 1;
        int tokb = b * LSEQ + c * SC_CH;
        const float* su = smf + SC_U  + buf * 4096 + tid;
        const float* sd = smf + SC_DT + buf * 4096 + tid;
        const float* sz = smf + SC_Z  + buf * 4096 + tid;
        const float* sB = smf + SC_B + buf * 512;
        const float* sC = smf + SC_C + buf * 512;
        if (fast) {
            for (int s = 0; s < SC_CH; s++) {
                float ut  = su[s * 128];
                float dtt = sd[s * 128];
                float z   = sz[s * 128];
                float du = dtt * ut;
                float e1 = __expf(-dtt);
                float e2 = e1 * e1, e3 = e2 * e1, e4 = e2 * e2;
                float e8 = e4 * e4, e12 = e8 * e4;
                float pw[DS] = {e1, e2, e3, e4,
                                e4 * e1, e4 * e2, e4 * e3, e8,
                                e8 * e1, e8 * e2, e8 * e3, e12,
                                e12 * e1, e12 * e2, e12 * e3, e8 * e8};
                float yv = 0.f;
#pragma unroll
                for (int n = 0; n < DS; n++) {
                    h[n] = pw[n] * h[n] + du * sB[s * 16 + n];
                    yv += h[n] * sC[s * 16 + n];
                }
                yv += ut * Dv;
                float y = yv * (z / (1.f + __expf(-z)));
                size_t o = (size_t)(tokb + s) * DI + d;
                split2(y, g_yh[o], g_yl[o]);
            }
        } else {
            for (int s = 0; s < SC_CH; s++) {
                float ut  = su[s * 128];
                float dtt = sd[s * 128];
                float z   = sz[s * 128];
                float du = dtt * ut;
                float yv = 0.f;
#pragma unroll
                for (int n = 0; n < DS; n++) {
                    h[n] = __expf(dtt * A[n]) * h[n] + du * sB[s * 16 + n];
                    yv += h[n] * sC[s * 16 + n];
                }
                yv += ut * Dv;
                float y = yv * (z / (1.f + __expf(-z)));
                size_t o = (size_t)(tokb + s) * DI + d;
                split2(y, g_yh[o], g_yl[o]);
            }
        }
        __syncthreads();
    }
#undef SC_ISSUE
}

// ---------------- x += LayerNorm(t0 + t1); optional fused gate / rowmask ----------------
__global__ void addln_k(const float* __restrict__ g, const float* __restrict__ bb,
                        const float* __restrict__ t0, const float* __restrict__ t1,
                        const float* __restrict__ gw, const float* __restrict__ gb,
                        int cntb_rst, int do_mask) {
    int tok = blockIdx.x;
    int tid = threadIdx.x;
    if (gw && tok == 0 && tid < NEXP) { g_cnt[tid] = 0; g_fill[tid] = 0; }
    if (cntb_rst && tok == 0 && tid < BATCH) g_cntb[tid] = 0;
    float* x = g_x + (size_t)tok * DM;
    float v[4]; float s = 0.f;
#pragma unroll
    for (int i = 0; i < 4; i++) {
        size_t o = (size_t)tok * DM + tid + i * 256;
        v[i] = t0[o] + t1[o];
        s += v[i];
    }
    __shared__ float sm[256];
    sm[tid] = s; __syncthreads();
    for (int st = 128; st > 0; st >>= 1) { if (tid < st) sm[tid] += sm[tid + st]; __syncthreads(); }
    float mean = sm[0] / DM;
    __syncthreads();
    float q = 0.f;
#pragma unroll
    for (int i = 0; i < 4; i++) { float dd = v[i] - mean; q += dd * dd; }
    sm[tid] = q; __syncthreads();
    for (int st = 128; st > 0; st >>= 1) { if (tid < st) sm[tid] += sm[tid + st]; __syncthreads(); }
    float rstd = rsqrtf(sm[0] / DM + 1e-5f);

    float nx[4]; float s2 = 0.f;
#pragma unroll
    for (int i = 0; i < 4; i++) {
        int d = tid + i * 256;
        nx[i] = x[d] + (v[i] - mean) * rstd * g[d] + bb[d];
        x[d] = nx[i];
        s2 += nx[i];
        split2(nx[i], g_xh[(size_t)tok * DM + d], g_xl[(size_t)tok * DM + d]);
    }

    if (do_mask) {
        __syncthreads();
        sm[tid] = s2; __syncthreads();
        for (int st = 128; st > 0; st >>= 1) { if (tid < st) sm[tid] += sm[tid + st]; __syncthreads(); }
        if (tid == 0) {
            float m = (sm[0] != 0.f) ? 1.f : 0.f;
            g_mask[tok] = m;
            if (m != 0.f) atomicAdd(&g_cntb[tok / LSEQ], 1);
        }
    }

    if (gw) {
        __shared__ float gsm[NEXP][256];
        float p[NEXP];
#pragma unroll
        for (int e = 0; e < NEXP; e++) p[e] = 0.f;
#pragma unroll
        for (int i = 0; i < 4; i++) {
            int d = tid + i * 256;
            float xv = nx[i];
#pragma unroll
            for (int e = 0; e < NEXP; e++) p[e] += xv * gw[e * DM + d];
        }
        __syncthreads();
#pragma unroll
        for (int e = 0; e < NEXP; e++) gsm[e][tid] = p[e];
        __syncthreads();
        for (int st = 128; st > 0; st >>= 1) {
            if (tid < st)
#pragma unroll
                for (int e = 0; e < NEXP; e++) gsm[e][tid] += gsm[e][tid + st];
            __syncthreads();
        }
        if (tid == 0) {
            float m = -1e30f; int bi = 0;
            float lg[NEXP];
#pragma unroll
            for (int e = 0; e < NEXP; e++) {
                lg[e] = gsm[e][0] + gb[e];
                if (lg[e] > m) { m = lg[e]; bi = e; }
            }
            float ssum = 0.f;
#pragma unroll
            for (int e = 0; e < NEXP; e++) ssum += __expf(lg[e] - m);
            g_eidx[tok] = bi;
            g_ew[tok] = 1.f / ssum;
            atomicAdd(&g_cnt[bi], 1);
        }
    }
}

// ---------------- moe1 combine ----------------
__global__ void moe1_comb(const float* __restrict__ b1) {
    int i = blockIdx.x * 256 + threadIdx.x;
    int r = i >> 10, col = i & 1023;
    int e = g_eidx[g_perm[r]];
    float v = g_pp[i] + g_pp[NTOK * HEXP + i] + b1[e * HEXP + col];
    v = fmaxf(v, 0.f);
    split2(v, g_hh[i], g_hl[i]);
}

__global__ void route_offsets_k() {
    if (threadIdx.x == 0) { int o = 0; for (int e = 0; e < NEXP; e++) { g_off[e] = o; o += g_cnt[e]; } }
}
__global__ void route_scatter_k() {
    int tok = blockIdx.x * 256 + threadIdx.x;
    if (tok < NTOK) {
        int e = g_eidx[tok];
        int p = g_off[e] + atomicAdd(&g_fill[e], 1);
        g_perm[p] = tok;
    }
}

// ---------------- pooling + head ----------------
__global__ void pool_k() {
    int b = blockIdx.x;
    int d = blockIdx.y * 256 + threadIdx.x;
    float acc = 0.f;
    for (int l = 0; l < LSEQ; l++)
        acc += g_x[(size_t)(b * LSEQ + l) * DM + d] * g_mask[b * LSEQ + l];
    g_pooled[b * DM + d] = acc / fmaxf((float)g_cntb[b], 1.f);
}

__global__ void head_k(const float* __restrict__ w1, const float* __restrict__ b1,
                       const float* __restrict__ w2, const float* __restrict__ b2,
                       float* __restrict__ out) {
    int b = blockIdx.x;
    int j = threadIdx.x;
    const float* p = g_pooled + b * DM;
    float acc = b1[j];
    for (int k = 0; k < DM; k++) acc += p[k] * w1[j * DM + k];
    __shared__ float h[128];
    h[j] = fmaxf(acc, 0.f);
    __syncthreads();
    if (j < 2) {
        float o = b2[j];
        for (int k = 0; k < 128; k++) o += h[k] * w2[j * 128 + k];
        out[b * 2 + j] = o;
    }
}

// ---------------- launch ----------------
extern "C" void kernel_launch(void* const* d_in, const int* in_sizes, int n_in,
                              void* d_out, int out_size) {
    const int*   tok    = (const int*)  d_in[0];
    const float* emb    = (const float*)d_in[1];
    const float* pos    = (const float*)d_in[2];
    const float* in_w   = (const float*)d_in[3];
    const float* conv_w = (const float*)d_in[4];
    const float* conv_b = (const float*)d_in[5];
    const float* xp_w   = (const float*)d_in[6];
    const float* dt_w   = (const float*)d_in[7];
    const float* dt_b   = (const float*)d_in[8];
    const float* A_log  = (const float*)d_in[9];
    const float* D_ssm  = (const float*)d_in[10];
    const float* out_w  = (const float*)d_in[11];
    const float* ln1_g  = (const float*)d_in[12];
    const float* ln1_b  = (const float*)d_in[13];
    const float* ln2_g  = (const float*)d_in[14];
    const float* ln2_b  = (const float*)d_in[15];
    const float* gate_w = (const float*)d_in[16];
    const float* gate_b = (const float*)d_in[17];
    const float* e_w1   = (const float*)d_in[18];
    const float* e_b1   = (const float*)d_in[19];
    const float* e_w2   = (const float*)d_in[20];
    const float* e_b2   = (const float*)d_in[21];
    const float* fc1_w  = (const float*)d_in[22];
    const float* fc1_b  = (const float*)d_in[23];
    const float* fc2_w  = (const float*)d_in[24];
    const float* fc2_b  = (const float*)d_in[25];
    float* out = (float*)d_out;

    cudaFuncSetAttribute(mma_gemm, cudaFuncAttributeMaxDynamicSharedMemorySize, SM_TOT);
    cudaFuncSetAttribute(ssm_scan_k, cudaFuncAttributeMaxDynamicSharedMemorySize, SC_SMEM);

    float *puz, *pxps, *pdt, *ppp, *pew;
    __half *pxh, *pxl, *puh, *pul, *pyh, *pyl, *phh, *phl, *pdah, *pdal;
    int *pcnt, *poff, *pperm;
    cudaGetSymbolAddress((void**)&puz,  g_uz);
    cudaGetSymbolAddress((void**)&pxps, g_xps);
    cudaGetSymbolAddress((void**)&pdt,  g_dt);
    cudaGetSymbolAddress((void**)&ppp,  g_pp);
    cudaGetSymbolAddress((void**)&pew,  g_ew);
    cudaGetSymbolAddress((void**)&pxh,  g_xh);
    cudaGetSymbolAddress((void**)&pxl,  g_xl);
    cudaGetSymbolAddress((void**)&puh,  g_uh);
    cudaGetSymbolAddress((void**)&pul,  g_ul);
    cudaGetSymbolAddress((void**)&pyh,  g_yh);
    cudaGetSymbolAddress((void**)&pyl,  g_yl);
    cudaGetSymbolAddress((void**)&phh,  g_hh);
    cudaGetSymbolAddress((void**)&phl,  g_hl);
    cudaGetSymbolAddress((void**)&pdah, g_dah);
    cudaGetSymbolAddress((void**)&pdal, g_dal);
    cudaGetSymbolAddress((void**)&pcnt, g_cnt);
    cudaGetSymbolAddress((void**)&poff, g_off);
    cudaGetSymbolAddress((void**)&pperm,g_perm);

    const int BIG = 1 << 30;

    embed_k<<<(NTOK * DM) / 256, 256>>>(tok, emb, pos);

    for (int l = 0; l < 2; l++) {
        const float* in_w_l  = in_w  + (size_t)l * 2 * DI * DM;
        const float* xp_w_l  = xp_w  + (size_t)l * XPD * DI;
        const float* dt_w_l  = dt_w  + (size_t)l * DI * DTR;
        const float* out_w_l = out_w + (size_t)l * DM * DI;
        const float* e_w1_l  = e_w1  + (size_t)l * NEXP * HEXP * DM;
        const float* e_w2_l  = e_w2  + (size_t)l * NEXP * DM * HEXP;
        const float* A_log_l = A_log + (size_t)l * DI * DS;
        int t2 = (l == 1) ? 2 : 3;
        // layer-2 in_proj: z-half (cols >= DI) gets 2-term (no scan downstream of layer-2 z)
        int in_t3lim = (l == 1) ? DI : BIG;

        // in_proj (u-half always 3-term: feeds the scan path)
        mma_gemm<<<dim3(32, 32, 1), 256, SM_TOT>>>(
            pxh, pxl, DM, in_w_l, DM, 0, puz, 2 * DI, 0, nullptr, nullptr,
            nullptr, 0, NTOK, nullptr, nullptr, nullptr, nullptr, 0, 2 * DI, DM, 32, 0, 3, in_t3lim);

        conv_silu_k<<<(NTOK * DI) / 256, 256>>>(conv_w + (size_t)l * DI * 4, conv_b + (size_t)l * DI);

        // xp: split-K x8 (3-term)
        mma_gemm<<<dim3(32, KSPL, 1), 256, SM_TOT>>>(
            puh, pul, DI, xp_w_l, DI, 0, pxps, XPD, (size_t)NTOK * XPD, nullptr, nullptr,
            nullptr, 0, NTOK, nullptr, nullptr, nullptr, nullptr, 0, XPD, DI / KSPL, 1, 0, 3, BIG);
        xp_reduce_dt_k<<<(NTOK * XPD) / 256, 256>>>();

        // dt (3-term)
        mma_gemm<<<dim3(32, 16, 1), 256, SM_TOT>>>(
            pdah, pdal, DTR, dt_w_l, DTR, 0, pdt, DI, 0, nullptr, nullptr,
            dt_b + (size_t)l * DI, 0, NTOK, nullptr, nullptr, nullptr, nullptr, 0, DI, DTR, 16, 2, 3, BIG);

        // single-pass scan
        ssm_scan_k<<<dim3(BATCH, DI / 128), 128, SC_SMEM>>>(
            A_log_l, D_ssm + (size_t)l * DI);

        // out: split-K x2
        mma_gemm<<<dim3(32, 16, 1), 256, SM_TOT>>>(
            pyh, pyl, DI, out_w_l, DI, 0, ppp, DM, (size_t)NTOK * DM, nullptr, nullptr,
            nullptr, 0, NTOK, nullptr, nullptr, nullptr, nullptr, 0, DM, DI / 2, 8, 0, t2, BIG);

        // x += LN(out) with fused gate; on layer 2 also reset cntb for later mask pass
        addln_k<<<NTOK, 256>>>(ln1_g + (size_t)l * DM, ln1_b + (size_t)l * DM,
                               ppp, ppp + (size_t)NTOK * DM,
                               gate_w + (size_t)l * NEXP * DM, gate_b + (size_t)l * NEXP,
                               (l == 1) ? 1 : 0, 0);

        route_offsets_k<<<1, 1>>>();
        route_scatter_k<<<NTOK / 256, 256>>>();

        // moe1: split-K x2 + combine
        mma_gemm<<<dim3(32, 16, NEXP), 256, SM_TOT>>>(
            pxh, pxl, DM, e_w1_l, DM, (size_t)HEXP * DM, ppp, HEXP, (size_t)NTOK * HEXP,
            nullptr, nullptr, nullptr, 0, 0, pcnt, poff, pperm, nullptr, 1, HEXP, DM / 2, 8, 0, t2, BIG);
        moe1_comb<<<(NTOK * HEXP) / 256, 256>>>(e_b1 + (size_t)l * NEXP * HEXP);

        // moe2: split-K x2
        mma_gemm<<<dim3(32, 16, NEXP), 256, SM_TOT>>>(
            phh, phl, HEXP, e_w2_l, HEXP, (size_t)DM * HEXP, ppp, DM, (size_t)NTOK * DM,
            nullptr, nullptr, e_b2 + (size_t)l * NEXP * DM, DM, 0, pcnt, poff, pperm, pew,
            2, DM, HEXP / 2, 8, 0, t2, BIG);

        // x += LN(moe); on last layer compute rowmask inline (cntb was reset at addln1)
        addln_k<<<NTOK, 256>>>(ln2_g + (size_t)l * DM, ln2_b + (size_t)l * DM,
                               ppp, ppp + (size_t)NTOK * DM, nullptr, nullptr,
                               0, (l == 1) ? 1 : 0);
    }

    pool_k<<<dim3(BATCH, DM / 256), 256>>>();
    head_k<<<BATCH, 128>>>(fc1_w, fc1_b, fc2_w, fc2_b, out);
}

// round 16
// speedup vs baseline: 1.0151x; 1.0016x over previous
#include <cuda_runtime.h>
#include <cuda_fp16.h>
#include <math.h>
#include <stdint.h>

// ---------------- problem constants ----------------
#define NTOK  4096
#define LSEQ  1024
#define BATCH 4
#define DM    1024
#define DI    2048
#define DS    16
#define DTR   64
#define XPD   96
#define NEXP  8
#define HEXP  1024
#define KSPL  8

// ---------------- device scratch ----------------
__device__ float g_x [NTOK*DM];
__device__ float g_uz[NTOK*2*DI];
__device__ float g_xp[NTOK*XPD];
__device__ float g_xps[KSPL*NTOK*XPD];
__device__ float g_dt[NTOK*DI];
__device__ float g_pp[2*NTOK*DM];
__device__ float g_mask[NTOK];
__device__ float g_pooled[BATCH*DM];
__device__ int   g_eidx[NTOK];
__device__ float g_ew  [NTOK];
__device__ int   g_perm[NTOK];
__device__ int   g_cnt[NEXP], g_off[NEXP], g_fill[NEXP], g_cntb[BATCH];

// fp16 hi/lo split buffers (activations only)
__device__ __half g_xh[NTOK*DM],  g_xl[NTOK*DM];
__device__ __half g_uh[NTOK*DI],  g_ul[NTOK*DI];
__device__ __half g_yh[NTOK*DI],  g_yl[NTOK*DI];
__device__ __half g_hh[NTOK*HEXP],g_hl[NTOK*HEXP];
__device__ __half g_dah[NTOK*DTR],g_dal[NTOK*DTR];

// ---------------- PTX helpers (base ISA only) ----------------
__device__ __forceinline__ uint32_t smem_u32(const void* p) {
    uint32_t a;
    asm("{ .reg .u64 t; cvta.to.shared.u64 t, %1; cvt.u32.u64 %0, t; }" : "=r"(a) : "l"(p));
    return a;
}
__device__ __forceinline__ void ldsm4(uint32_t* r, uint32_t addr) {
    asm volatile("ldmatrix.sync.aligned.m8n8.x4.shared.b16 {%0,%1,%2,%3}, [%4];"
        : "=r"(r[0]), "=r"(r[1]), "=r"(r[2]), "=r"(r[3]) : "r"(addr));
}
__device__ __forceinline__ void mma_f16(float* c, const uint32_t* a, uint32_t b0, uint32_t b1) {
    asm volatile("mma.sync.aligned.m16n8k16.row.col.f32.f16.f16.f32 "
        "{%0,%1,%2,%3}, {%4,%5,%6,%7}, {%8,%9}, {%0,%1,%2,%3};"
        : "+f"(c[0]), "+f"(c[1]), "+f"(c[2]), "+f"(c[3])
        : "r"(a[0]), "r"(a[1]), "r"(a[2]), "r"(a[3]), "r"(b0), "r"(b1));
}
__device__ __forceinline__ void cpa16(uint32_t saddr, const void* g, bool v) {
    int sz = v ? 16 : 0;
    asm volatile("cp.async.cg.shared.global [%0], [%1], 16, %2;"
        :: "r"(saddr), "l"(g), "r"(sz));
}
__device__ __forceinline__ void cpa16f(uint32_t saddr, const void* g) {
    asm volatile("cp.async.cg.shared.global [%0], [%1], 16;"
        :: "r"(saddr), "l"(g));
}
#define CP_COMMIT() asm volatile("cp.async.commit_group;" ::: "memory")
#define CP_WAIT1()  asm volatile("cp.async.wait_group 1;" ::: "memory")
#define CP_WAIT0()  asm volatile("cp.async.wait_group 0;" ::: "memory")

// smem geometry: K-chunk 32 fp16 = 64B/row, padded to 80B
#define ROWB   80
#define TILEB  10240
#define STAGEB 40960
#define SM_TOT 81920

// ============ fused-split fp16 mma.sync GEMM ============
// terms==3: Ah*Wh + Al*Wh + Ah*Wl (3rd term only for n0 < t3lim).  terms==2: Ah*Wh + Al*Wh.
__global__ void __launch_bounds__(256, 2)
mma_gemm(const __half* __restrict__ Ah, const __half* __restrict__ Al, int lda,
         const float* __restrict__ W32, int ldw, size_t wz,
         float* __restrict__ C, int ldc, size_t czs,
         __half* __restrict__ Ch, __half* __restrict__ Cl,
         const float* __restrict__ bias, int bias_z,
         int M_fixed, const int* __restrict__ cntp, const int* __restrict__ offp,
         const int* __restrict__ perm, const float* __restrict__ rowscale,
         int mode, int N, int K, int nyb, int act, int terms, int t3lim)
{
    int e = blockIdx.z;
    int M = cntp ? cntp[e] : M_fixed;
    int base = offp ? offp[e] : 0;
    int yy = blockIdx.y;
    int ks = yy / nyb;
    int nb = yy - ks * nyb;
    int bx = blockIdx.x;

    // raster swizzle: 4-wide m-supertiles for L2 locality
    {
        int nbx = gridDim.x;
        if (nbx >= 4) {
            int lin = nb * nbx + bx;
            int sw = 4 * nyb;
            int stile = lin / sw;
            int rem = lin - stile * sw;
            int m_in = rem % 4;
            int n_in = rem / 4;
            int mb = stile * 4 + m_in;
            if (mb < nbx) { bx = mb; nb = n_in; }
        }
    }

    int m0 = bx * 128;
    if (m0 >= M) return;
    int n0 = nb * 128;
    int use3 = (terms == 3) && (n0 < t3lim);

    extern __shared__ char smem[];
    uint32_t sb = smem_u32(smem);
    int tid = threadIdx.x;

    int sub = tid & 3;
    int r0 = tid >> 2;
    size_t aoff[2]; uint32_t avm = 0;
#pragma unroll
    for (int i = 0; i < 2; i++) {
        int mm = m0 + r0 + 64 * i;
        bool av = mm < M;
        if (av) avm |= 1u << i;
        int ar;
        if (mode == 1)      ar = av ? perm[base + mm] : 0;
        else if (mode == 2) ar = base + (av ? mm : 0);
        else                ar = av ? mm : 0;
        aoff[i] = (size_t)ar * lda + sub * 8 + (size_t)ks * K;
    }
    uint32_t srow0 = r0 * ROWB + sub * 16;
    uint32_t srow1 = (r0 + 64) * ROWB + sub * 16;

    int wrow_l = tid >> 1;
    int wn = n0 + wrow_l;
    if (wn >= N) wn = 0;
    int khalf = (tid & 1) * 16;
    const float* WE = W32 + (size_t)e * wz + (size_t)wn * ldw + khalf + (size_t)ks * K;
    uint32_t wsts = (uint32_t)wrow_l * ROWB + (tid & 1) * 32;

    const int NC = K / 32;
    float4 wr[4];

#define COPY_A(c, s) do { \
        int _k0 = (c) * 32; \
        uint32_t _sB = sb + (uint32_t)(s) * STAGEB; \
        cpa16(_sB + srow0,         Ah + aoff[0] + _k0, avm & 1); \
        cpa16(_sB + srow1,         Ah + aoff[1] + _k0, (avm >> 1) & 1); \
        cpa16(_sB + TILEB + srow0, Al + aoff[0] + _k0, avm & 1); \
        cpa16(_sB + TILEB + srow1, Al + aoff[1] + _k0, (avm >> 1) & 1); \
    } while (0)

#define W_LDG(c) do { \
        const float4* _wp = reinterpret_cast<const float4*>(WE + (size_t)(c) * 32); \
        wr[0] = _wp[0]; wr[1] = _wp[1]; wr[2] = _wp[2]; wr[3] = _wp[3]; \
    } while (0)

#define W_STS(s) do { \
        float _wv[16]; \
        *(float4*)&_wv[0] = wr[0]; *(float4*)&_wv[4] = wr[1]; \
        *(float4*)&_wv[8] = wr[2]; *(float4*)&_wv[12] = wr[3]; \
        __half _hh[16]; \
        _Pragma("unroll") \
        for (int _i = 0; _i < 16; _i++) _hh[_i] = __float2half_rn(_wv[_i]); \
        char* _wh = smem + (uint32_t)(s) * STAGEB + 2 * TILEB + wsts; \
        *(uint4*)(_wh)      = *(uint4*)&_hh[0]; \
        *(uint4*)(_wh + 16) = *(uint4*)&_hh[8]; \
        if (use3) { \
            __half _hl[16]; \
            _Pragma("unroll") \
            for (int _i = 0; _i < 16; _i++) \
                _hl[_i] = __float2half_rn(_wv[_i] - __half2float(_hh[_i])); \
            char* _wl = smem + (uint32_t)(s) * STAGEB + 3 * TILEB + wsts; \
            *(uint4*)(_wl)      = *(uint4*)&_hl[0]; \
            *(uint4*)(_wl + 16) = *(uint4*)&_hl[8]; \
        } \
    } while (0)

    int lane = tid & 31;
    int wid = tid >> 5;
    int wm = (wid & 3) * 32;
    int wn2 = (wid >> 2) * 64;

    uint32_t aRB = (uint32_t)(wm + (lane & 7) + ((lane >> 3) & 1) * 8) * ROWB + ((lane >> 4) & 1) * 16;
    uint32_t bRB = (uint32_t)(wn2 + (lane & 7) + ((lane >> 4) & 1) * 8) * ROWB + ((lane >> 3) & 1) * 16;

    float acc[2][8][4] = {};

    COPY_A(0, 0); CP_COMMIT();
    W_LDG(0);

    for (int c = 0; c < NC; c++) {
        if (c + 1 < NC) { COPY_A(c + 1, (c + 1) & 1); CP_COMMIT(); }
        W_STS(c & 1);
        if (c + 1 < NC) CP_WAIT1(); else CP_WAIT0();
        __syncthreads();
        if (c + 1 < NC) W_LDG(c + 1);

        uint32_t AhB = sb + (uint32_t)(c & 1) * STAGEB;
        uint32_t AlB = AhB + TILEB;
        uint32_t WhB = AhB + 2 * TILEB;
        uint32_t WlB = AhB + 3 * TILEB;
#pragma unroll
        for (int st = 0; st < 2; st++) {
            uint32_t kB = st * 32;
            uint32_t ah[2][4], al[2][4], bb[4][4];
#pragma unroll
            for (int im = 0; im < 2; im++)
                ldsm4(ah[im], AhB + (uint32_t)(im * 16) * ROWB + aRB + kB);
#pragma unroll
            for (int g = 0; g < 4; g++)
                ldsm4(bb[g], WhB + (uint32_t)(g * 16) * ROWB + bRB + kB);
#pragma unroll
            for (int im = 0; im < 2; im++)
#pragma unroll
                for (int in = 0; in < 8; in++)
                    mma_f16(acc[im][in], ah[im], bb[in >> 1][(in & 1) * 2], bb[in >> 1][(in & 1) * 2 + 1]);
#pragma unroll
            for (int im = 0; im < 2; im++)
                ldsm4(al[im], AlB + (uint32_t)(im * 16) * ROWB + aRB + kB);
#pragma unroll
            for (int im = 0; im < 2; im++)
#pragma unroll
                for (int in = 0; in < 8; in++)
                    mma_f16(acc[im][in], al[im], bb[in >> 1][(in & 1) * 2], bb[in >> 1][(in & 1) * 2 + 1]);
            if (use3) {
#pragma unroll
                for (int g = 0; g < 4; g++)
                    ldsm4(bb[g], WlB + (uint32_t)(g * 16) * ROWB + bRB + kB);
#pragma unroll
                for (int im = 0; im < 2; im++)
#pragma unroll
                    for (int in = 0; in < 8; in++)
                        mma_f16(acc[im][in], ah[im], bb[in >> 1][(in & 1) * 2], bb[in >> 1][(in & 1) * 2 + 1]);
            }
        }
        __syncthreads();
    }

    // ---- epilogue ----
    int lq = lane >> 2;
    int lr = lane & 3;
    const float* bp = (bias && ks == 0) ? (bias + (size_t)e * bias_z) : nullptr;
    float* Cz = C ? (C + (size_t)ks * czs) : C;
#pragma unroll
    for (int im = 0; im < 2; im++) {
#pragma unroll
        for (int r2 = 0; r2 < 2; r2++) {
            int m = m0 + wm + im * 16 + lq + r2 * 8;
            if (m >= M) continue;
            long crow; float scale = 1.f;
            if (mode == 2)      { crow = perm[base + m]; scale = rowscale[crow]; }
            else if (mode == 1) { crow = base + m; }
            else                { crow = m; }
#pragma unroll
            for (int in = 0; in < 8; in++) {
                int n = n0 + wn2 + in * 8 + lr * 2;
                if (n >= N) continue;
                float v0 = acc[im][in][r2 * 2 + 0];
                float v1 = acc[im][in][r2 * 2 + 1];
                if (bp) { v0 += bp[n]; v1 += bp[n + 1]; }
                if (act == 1) { v0 = fmaxf(v0, 0.f); v1 = fmaxf(v1, 0.f); }
                else if (act == 2) {
                    v0 = (v0 > 20.f) ? v0 : log1pf(__expf(v0));
                    v1 = (v1 > 20.f) ? v1 : log1pf(__expf(v1));
                }
                if (Ch) {
                    __half h0 = __float2half_rn(v0);
                    __half h1 = __float2half_rn(v1);
                    size_t o = (size_t)crow * ldc + n;
                    Ch[o] = h0;     Cl[o]     = __float2half_rn(v0 - __half2float(h0));
                    Ch[o + 1] = h1; Cl[o + 1] = __float2half_rn(v1 - __half2float(h1));
                } else {
                    size_t o = (size_t)crow * ldc + n;
                    Cz[o] = v0 * scale;
                    Cz[o + 1] = v1 * scale;
                }
            }
        }
    }
#undef COPY_A
#undef W_LDG
#undef W_STS
}

// ---------------- fp16 split helpers ----------------
__device__ __forceinline__ void split2(float v, __half& h, __half& l) {
    h = __float2half_rn(v);
    l = __float2half_rn(v - __half2float(h));
}

// fused split-K reduce for xp + dt-input conversion
__global__ void xp_reduce_dt_k() {
    int i = blockIdx.x * 256 + threadIdx.x;
    float s = 0.f;
#pragma unroll
    for (int j = 0; j < KSPL; j++) s += g_xps[(size_t)j * NTOK * XPD + i];
    g_xp[i] = s;
    int t = i / XPD, c = i - t * XPD;
    if (c < DTR) {
        int o = t * DTR + c;
        split2(s, g_dah[o], g_dal[o]);
    }
}

// ---------------- embed ----------------
__global__ void embed_k(const int* __restrict__ tok, const float* __restrict__ emb,
                        const float* __restrict__ pos) {
    int i = blockIdx.x * blockDim.x + threadIdx.x;
    int t = i / DM, d = i % DM;
    int l = t % LSEQ;
    float v = emb[(size_t)tok[t] * DM + d] + pos[l * DM + d];
    g_x[i] = v;
    split2(v, g_xh[i], g_xl[i]);
}

// ---------------- smem-tiled conv + silu -> fp16 pair only ----------------
// grid (NTOK/64, DI/128), 256 threads. Tile: 64 tokens x 128 d; stages 67 uz rows once.
__global__ void __launch_bounds__(256) conv_silu_k(const float* __restrict__ cw,
                                                   const float* __restrict__ cb) {
    __shared__ float sm[67][128];
    int tokb = blockIdx.x * 64;
    int d0 = blockIdx.y * 128;
    int tid = threadIdx.x;
    int bstart = (tokb / LSEQ) * LSEQ;     // tile never crosses batch boundary (1024 % 64 == 0)

    for (int i = tid; i < 67 * 128; i += 256) {
        int r = i >> 7, dcol = i & 127;
        int tr = tokb - 3 + r;
        sm[r][dcol] = (tr >= bstart) ? g_uz[(size_t)tr * (2 * DI) + d0 + dcol] : 0.f;
    }
    __syncthreads();

    int dcol = tid & 127;
    int d = d0 + dcol;
    float4 w4 = *(const float4*)(cw + d * 4);
    float bv = cb[d];
    int sbase = tid >> 7;                  // 0 or 1
#pragma unroll
    for (int it = 0; it < 32; it++) {
        int s = sbase + it * 2;
        float acc = bv + sm[s][dcol] * w4.x + sm[s + 1][dcol] * w4.y
                       + sm[s + 2][dcol] * w4.z + sm[s + 3][dcol] * w4.w;
        float v = acc / (1.f + __expf(-acc));
        size_t o = (size_t)(tokb + s) * DI + d;
        split2(v, g_uh[o], g_ul[o]);
    }
}

// ---------------- A structure detection: A[n] == -(n+1)? ----------------
__device__ __forceinline__ bool load_A(const float* A_log, int d, float* A) {
    bool fast = true;
#pragma unroll
    for (int n = 0; n < DS; n++) {
        A[n] = -expf(A_log[d * DS + n]);
        fast = fast && (fabsf(A[n] + (float)(n + 1)) < 1e-4f);
    }
    return fast;
}

// ---------------- single-pass selective scan with cp.async staging ----------------
// u is reconstructed from the fp16 pair (uh + ul): exact to ~2^-22, no fp32 u buffer.
// smem bytes: UH[2][32][128]h UL[..]h DT[2][32][128]f Z[..]f B[2][32][16]f C[..]f
#define SC_CH   32
#define SC_NC   (LSEQ / SC_CH)
#define SC_UH   0
#define SC_UL   16384
#define SC_DT   32768
#define SC_Z    65536
#define SC_B    98304
#define SC_C    102400
#define SC_SMEM 106496

__global__ void __launch_bounds__(128) ssm_scan_k(const float* __restrict__ A_log,
                                                  const float* __restrict__ Dp) {
    int b = blockIdx.x;
    int d0 = blockIdx.y * 128;
    int tid = threadIdx.x;
    int d = d0 + tid;

    float A[DS];
    bool fast = load_A(A_log, d, A);
    float Dv = Dp[d];
    float h[DS];
#pragma unroll
    for (int n = 0; n < DS; n++) h[n] = 0.f;

    extern __shared__ char smc[];
    uint32_t sbase = smem_u32(smc);

#define SC_ISSUE(c) do { \
        int _buf = (c) & 1; \
        int _tokb = b * LSEQ + (c) * SC_CH; \
        _Pragma("unroll") \
        for (int _j = 0; _j < 4; _j++) { \
            int _q = _j * 128 + tid; \
            int _s = _q >> 4, _hq = (_q & 15) * 8; \
            uint32_t _o = (uint32_t)(_buf * 8192 + _s * 256 + _hq * 2); \
            cpa16f(sbase + SC_UH + _o, g_uh + (size_t)(_tokb + _s) * DI + d0 + _hq); \
            cpa16f(sbase + SC_UL + _o, g_ul + (size_t)(_tokb + _s) * DI + d0 + _hq); \
        } \
        _Pragma("unroll") \
        for (int _j = 0; _j < 8; _j++) { \
            int _q = _j * 128 + tid; \
            int _s = _q >> 5, _qd = (_q & 31) * 4; \
            uint32_t _o = (uint32_t)(_buf * 16384 + _s * 512 + _qd * 4); \
            cpa16f(sbase + SC_DT + _o, g_dt + (size_t)(_tokb + _s) * DI + d0 + _qd); \
            cpa16f(sbase + SC_Z  + _o, g_uz + (size_t)(_tokb + _s) * (2 * DI) + DI + d0 + _qd); \
        } \
        { int _s = tid >> 2, _qd = (tid & 3) * 4; \
          uint32_t _o = (uint32_t)(_buf * 2048 + _s * 64 + _qd * 4); \
          cpa16f(sbase + SC_B + _o, g_xp + (size_t)(_tokb + _s) * XPD + DTR + _qd); \
          cpa16f(sbase + SC_C + _o, g_xp + (size_t)(_tokb + _s) * XPD + DTR + DS + _qd); } \
        CP_COMMIT(); \
    } while (0)

    SC_ISSUE(0);
    for (int c = 0; c < SC_NC; c++) {
        if (c + 1 < SC_NC) SC_ISSUE(c + 1);
        if (c + 1 < SC_NC) CP_WAIT1(); else CP_WAIT0();
        __syncthreads();
        int buf = c & 1;
        int tokb = b * LSEQ + c * SC_CH;
        const __half* suh = (const __half*)(smc + SC_UH + buf * 8192) + tid;
        const __half* sul = (const __half*)(smc + SC_UL + buf * 8192) + tid;
        const float* sd = (const float*)(smc + SC_DT + buf * 16384) + tid;
        const float* sz = (const float*)(smc + SC_Z  + buf * 16384) + tid;
        const float* sB = (const float*)(smc + SC_B + buf * 2048);
        const float* sC = (const float*)(smc + SC_C + buf * 2048);
        if (fast) {
            for (int s = 0; s < SC_CH; s++) {
                float ut  = __half2float(suh[s * 128]) + __half2float(sul[s * 128]);
                float dtt = sd[s * 128];
                float z   = sz[s * 128];
                float du = dtt * ut;
                float e1 = __expf(-dtt);
                float e2 = e1 * e1, e3 = e2 * e1, e4 = e2 * e2;
                float e8 = e4 * e4, e12 = e8 * e4;
                float pw[DS] = {e1, e2, e3, e4,
                                e4 * e1, e4 * e2, e4 * e3, e8,
                                e8 * e1, e8 * e2, e8 * e3, e12,
                                e12 * e1, e12 * e2, e12 * e3, e8 * e8};
                float yv = 0.f;
#pragma unroll
                for (int n = 0; n < DS; n++) {
                    h[n] = pw[n] * h[n] + du * sB[s * 16 + n];
                    yv += h[n] * sC[s * 16 + n];
                }
                yv += ut * Dv;
                float y = yv * (z / (1.f + __expf(-z)));
                size_t o = (size_t)(tokb + s) * DI + d;
                split2(y, g_yh[o], g_yl[o]);
            }
        } else {
            for (int s = 0; s < SC_CH; s++) {
                float ut  = __half2float(suh[s * 128]) + __half2float(sul[s * 128]);
                float dtt = sd[s * 128];
                float z   = sz[s * 128];
                float du = dtt * ut;
                float yv = 0.f;
#pragma unroll
                for (int n = 0; n < DS; n++) {
                    h[n] = __expf(dtt * A[n]) * h[n] + du * sB[s * 16 + n];
                    yv += h[n] * sC[s * 16 + n];
                }
                yv += ut * Dv;
                float y = yv * (z / (1.f + __expf(-z)));
                size_t o = (size_t)(tokb + s) * DI + d;
                split2(y, g_yh[o], g_yl[o]);
            }
        }
        __syncthreads();
    }
#undef SC_ISSUE
}

// ---------------- x += LayerNorm(t0 + t1); optional fused gate / rowmask ----------------
__global__ void addln_k(const float* __restrict__ g, const float* __restrict__ bb,
                        const float* __restrict__ t0, const float* __restrict__ t1,
                        const float* __restrict__ gw, const float* __restrict__ gb,
                        int cntb_rst, int do_mask) {
    int tok = blockIdx.x;
    int tid = threadIdx.x;
    if (gw && tok == 0 && tid < NEXP) { g_cnt[tid] = 0; g_fill[tid] = 0; }
    if (cntb_rst && tok == 0 && tid < BATCH) g_cntb[tid] = 0;
    float* x = g_x + (size_t)tok * DM;
    float v[4]; float s = 0.f;
#pragma unroll
    for (int i = 0; i < 4; i++) {
        size_t o = (size_t)tok * DM + tid + i * 256;
        v[i] = t0[o] + t1[o];
        s += v[i];
    }
    __shared__ float sm[256];
    sm[tid] = s; __syncthreads();
    for (int st = 128; st > 0; st >>= 1) { if (tid < st) sm[tid] += sm[tid + st]; __syncthreads(); }
    float mean = sm[0] / DM;
    __syncthreads();
    float q = 0.f;
#pragma unroll
    for (int i = 0; i < 4; i++) { float dd = v[i] - mean; q += dd * dd; }
    sm[tid] = q; __syncthreads();
    for (int st = 128; st > 0; st >>= 1) { if (tid < st) sm[tid] += sm[tid + st]; __syncthreads(); }
    float rstd = rsqrtf(sm[0] / DM + 1e-5f);

    float nx[4]; float s2 = 0.f;
#pragma unroll
    for (int i = 0; i < 4; i++) {
        int d = tid + i * 256;
        nx[i] = x[d] + (v[i] - mean) * rstd * g[d] + bb[d];
        x[d] = nx[i];
        s2 += nx[i];
        split2(nx[i], g_xh[(size_t)tok * DM + d], g_xl[(size_t)tok * DM + d]);
    }

    if (do_mask) {
        __syncthreads();
        sm[tid] = s2; __syncthreads();
        for (int st = 128; st > 0; st >>= 1) { if (tid < st) sm[tid] += sm[tid + st]; __syncthreads(); }
        if (tid == 0) {
            float m = (sm[0] != 0.f) ? 1.f : 0.f;
            g_mask[tok] = m;
            if (m != 0.f) atomicAdd(&g_cntb[tok / LSEQ], 1);
        }
    }

    if (gw) {
        __shared__ float gsm[NEXP][256];
        float p[NEXP];
#pragma unroll
        for (int e = 0; e < NEXP; e++) p[e] = 0.f;
#pragma unroll
        for (int i = 0; i < 4; i++) {
            int d = tid + i * 256;
            float xv = nx[i];
#pragma unroll
            for (int e = 0; e < NEXP; e++) p[e] += xv * gw[e * DM + d];
        }
        __syncthreads();
#pragma unroll
        for (int e = 0; e < NEXP; e++) gsm[e][tid] = p[e];
        __syncthreads();
        for (int st = 128; st > 0; st >>= 1) {
            if (tid < st)
#pragma unroll
                for (int e = 0; e < NEXP; e++) gsm[e][tid] += gsm[e][tid + st];
            __syncthreads();
        }
        if (tid == 0) {
            float m = -1e30f; int bi = 0;
            float lg[NEXP];
#pragma unroll
            for (int e = 0; e < NEXP; e++) {
                lg[e] = gsm[e][0] + gb[e];
                if (lg[e] > m) { m = lg[e]; bi = e; }
            }
            float ssum = 0.f;
#pragma unroll
            for (int e = 0; e < NEXP; e++) ssum += __expf(lg[e] - m);
            g_eidx[tok] = bi;
            g_ew[tok] = 1.f / ssum;
            atomicAdd(&g_cnt[bi], 1);
        }
    }
}

// ---------------- moe1 combine ----------------
__global__ void moe1_comb(const float* __restrict__ b1) {
    int i = blockIdx.x * 256 + threadIdx.x;
    int r = i >> 10, col = i & 1023;
    int e = g_eidx[g_perm[r]];
    float v = g_pp[i] + g_pp[NTOK * HEXP + i] + b1[e * HEXP + col];
    v = fmaxf(v, 0.f);
    split2(v, g_hh[i], g_hl[i]);
}

__global__ void route_offsets_k() {
    if (threadIdx.x == 0) { int o = 0; for (int e = 0; e < NEXP; e++) { g_off[e] = o; o += g_cnt[e]; } }
}
__global__ void route_scatter_k() {
    int tok = blockIdx.x * 256 + threadIdx.x;
    if (tok < NTOK) {
        int e = g_eidx[tok];
        int p = g_off[e] + atomicAdd(&g_fill[e], 1);
        g_perm[p] = tok;
    }
}

// ---------------- pooling + head ----------------
__global__ void pool_k() {
    int b = blockIdx.x;
    int d = blockIdx.y * 256 + threadIdx.x;
    float acc = 0.f;
    for (int l = 0; l < LSEQ; l++)
        acc += g_x[(size_t)(b * LSEQ + l) * DM + d] * g_mask[b * LSEQ + l];
    g_pooled[b * DM + d] = acc / fmaxf((float)g_cntb[b], 1.f);
}

__global__ void head_k(const float* __restrict__ w1, const float* __restrict__ b1,
                       const float* __restrict__ w2, const float* __restrict__ b2,
                       float* __restrict__ out) {
    int b = blockIdx.x;
    int j = threadIdx.x;
    const float* p = g_pooled + b * DM;
    float acc = b1[j];
    for (int k = 0; k < DM; k++) acc += p[k] * w1[j * DM + k];
    __shared__ float h[128];
    h[j] = fmaxf(acc, 0.f);
    __syncthreads();
    if (j < 2) {
        float o = b2[j];
        for (int k = 0; k < 128; k++) o += h[k] * w2[j * 128 + k];
        out[b * 2 + j] = o;
    }
}

// ---------------- launch ----------------
extern "C" void kernel_launch(void* const* d_in, const int* in_sizes, int n_in,
                              void* d_out, int out_size) {
    const int*   tok    = (const int*)  d_in[0];
    const float* emb    = (const float*)d_in[1];
    const float* pos    = (const float*)d_in[2];
    const float* in_w   = (const float*)d_in[3];
    const float* conv_w = (const float*)d_in[4];
    const float* conv_b = (const float*)d_in[5];
    const float* xp_w   = (const float*)d_in[6];
    const float* dt_w   = (const float*)d_in[7];
    const float* dt_b   = (const float*)d_in[8];
    const float* A_log  = (const float*)d_in[9];
    const float* D_ssm  = (const float*)d_in[10];
    const float* out_w  = (const float*)d_in[11];
    const float* ln1_g  = (const float*)d_in[12];
    const float* ln1_b  = (const float*)d_in[13];
    const float* ln2_g  = (const float*)d_in[14];
    const float* ln2_b  = (const float*)d_in[15];
    const float* gate_w = (const float*)d_in[16];
    const float* gate_b = (const float*)d_in[17];
    const float* e_w1   = (const float*)d_in[18];
    const float* e_b1   = (const float*)d_in[19];
    const float* e_w2   = (const float*)d_in[20];
    const float* e_b2   = (const float*)d_in[21];
    const float* fc1_w  = (const float*)d_in[22];
    const float* fc1_b  = (const float*)d_in[23];
    const float* fc2_w  = (const float*)d_in[24];
    const float* fc2_b  = (const float*)d_in[25];
    float* out = (float*)d_out;

    cudaFuncSetAttribute(mma_gemm, cudaFuncAttributeMaxDynamicSharedMemorySize, SM_TOT);
    cudaFuncSetAttribute(ssm_scan_k, cudaFuncAttributeMaxDynamicSharedMemorySize, SC_SMEM);

    float *puz, *pxps, *pdt, *ppp, *pew;
    __half *pxh, *pxl, *puh, *pul, *pyh, *pyl, *phh, *phl, *pdah, *pdal;
    int *pcnt, *poff, *pperm;
    cudaGetSymbolAddress((void**)&puz,  g_uz);
    cudaGetSymbolAddress((void**)&pxps, g_xps);
    cudaGetSymbolAddress((void**)&pdt,  g_dt);
    cudaGetSymbolAddress((void**)&ppp,  g_pp);
    cudaGetSymbolAddress((void**)&pew,  g_ew);
    cudaGetSymbolAddress((void**)&pxh,  g_xh);
    cudaGetSymbolAddress((void**)&pxl,  g_xl);
    cudaGetSymbolAddress((void**)&puh,  g_uh);
    cudaGetSymbolAddress((void**)&pul,  g_ul);
    cudaGetSymbolAddress((void**)&pyh,  g_yh);
    cudaGetSymbolAddress((void**)&pyl,  g_yl);
    cudaGetSymbolAddress((void**)&phh,  g_hh);
    cudaGetSymbolAddress((void**)&phl,  g_hl);
    cudaGetSymbolAddress((void**)&pdah, g_dah);
    cudaGetSymbolAddress((void**)&pdal, g_dal);
    cudaGetSymbolAddress((void**)&pcnt, g_cnt);
    cudaGetSymbolAddress((void**)&poff, g_off);
    cudaGetSymbolAddress((void**)&pperm,g_perm);

    const int BIG = 1 << 30;

    embed_k<<<(NTOK * DM) / 256, 256>>>(tok, emb, pos);

    for (int l = 0; l < 2; l++) {
        const float* in_w_l  = in_w  + (size_t)l * 2 * DI * DM;
        const float* xp_w_l  = xp_w  + (size_t)l * XPD * DI;
        const float* dt_w_l  = dt_w  + (size_t)l * DI * DTR;
        const float* out_w_l = out_w + (size_t)l * DM * DI;
        const float* e_w1_l  = e_w1  + (size_t)l * NEXP * HEXP * DM;
        const float* e_w2_l  = e_w2  + (size_t)l * NEXP * DM * HEXP;
        const float* A_log_l = A_log + (size_t)l * DI * DS;
        int t2 = (l == 1) ? 2 : 3;
        int in_t3lim = (l == 1) ? DI : BIG;

        // in_proj (u-half always 3-term: feeds the scan path)
        mma_gemm<<<dim3(32, 32, 1), 256, SM_TOT>>>(
            pxh, pxl, DM, in_w_l, DM, 0, puz, 2 * DI, 0, nullptr, nullptr,
            nullptr, 0, NTOK, nullptr, nullptr, nullptr, nullptr, 0, 2 * DI, DM, 32, 0, 3, in_t3lim);

        conv_silu_k<<<dim3(NTOK / 64, DI / 128), 256>>>(conv_w + (size_t)l * DI * 4,
                                                        conv_b + (size_t)l * DI);

        // xp: split-K x8 (3-term)
        mma_gemm<<<dim3(32, KSPL, 1), 256, SM_TOT>>>(
            puh, pul, DI, xp_w_l, DI, 0, pxps, XPD, (size_t)NTOK * XPD, nullptr, nullptr,
            nullptr, 0, NTOK, nullptr, nullptr, nullptr, nullptr, 0, XPD, DI / KSPL, 1, 0, 3, BIG);
        xp_reduce_dt_k<<<(NTOK * XPD) / 256, 256>>>();

        // dt (3-term)
        mma_gemm<<<dim3(32, 16, 1), 256, SM_TOT>>>(
            pdah, pdal, DTR, dt_w_l, DTR, 0, pdt, DI, 0, nullptr, nullptr,
            dt_b + (size_t)l * DI, 0, NTOK, nullptr, nullptr, nullptr, nullptr, 0, DI, DTR, 16, 2, 3, BIG);

        // single-pass scan (u from fp16 pair)
        ssm_scan_k<<<dim3(BATCH, DI / 128), 128, SC_SMEM>>>(
            A_log_l, D_ssm + (size_t)l * DI);

        // out: split-K x2
        mma_gemm<<<dim3(32, 16, 1), 256, SM_TOT>>>(
            pyh, pyl, DI, out_w_l, DI, 0, ppp, DM, (size_t)NTOK * DM, nullptr, nullptr,
            nullptr, 0, NTOK, nullptr, nullptr, nullptr, nullptr, 0, DM, DI / 2, 8, 0, t2, BIG);

        // x += LN(out) with fused gate; on layer 2 also reset cntb for mask pass
        addln_k<<<NTOK, 256>>>(ln1_g + (size_t)l * DM, ln1_b + (size_t)l * DM,
                               ppp, ppp + (size_t)NTOK * DM,
                               gate_w + (size_t)l * NEXP * DM, gate_b + (size_t)l * NEXP,
                               (l == 1) ? 1 : 0, 0);

        route_offsets_k<<<1, 1>>>();
        route_scatter_k<<<NTOK / 256, 256>>>();

        // moe1: split-K x2 + combine
        mma_gemm<<<dim3(32, 16, NEXP), 256, SM_TOT>>>(
            pxh, pxl, DM, e_w1_l, DM, (size_t)HEXP * DM, ppp, HEXP, (size_t)NTOK * HEXP,
            nullptr, nullptr, nullptr, 0, 0, pcnt, poff, pperm, nullptr, 1, HEXP, DM / 2, 8, 0, t2, BIG);
        moe1_comb<<<(NTOK * HEXP) / 256, 256>>>(e_b1 + (size_t)l * NEXP * HEXP);

        // moe2: split-K x2
        mma_gemm<<<dim3(32, 16, NEXP), 256, SM_TOT>>>(
            phh, phl, HEXP, e_w2_l, HEXP, (size_t)DM * HEXP, ppp, DM, (size_t)NTOK * DM,
            nullptr, nullptr, e_b2 + (size_t)l * NEXP * DM, DM, 0, pcnt, poff, pperm, pew,
            2, DM, HEXP / 2, 8, 0, t2, BIG);

        // x += LN(moe); on last layer compute rowmask inline
        addln_k<<<NTOK, 256>>>(ln2_g + (size_t)l * DM, ln2_b + (size_t)l * DM,
                               ppp, ppp + (size_t)NTOK * DM, nullptr, nullptr,
                               0, (l == 1) ? 1 : 0);
    }

    pool_k<<<dim3(BATCH, DM / 256), 256>>>();
    head_k<<<BATCH, 128>>>(fc1_w, fc1_b, fc2_w, fc2_b, out);
}

// round 17
// speedup vs baseline: 1.0322x; 1.0168x over previous
#include <cuda_runtime.h>
#include <cuda_fp16.h>
#include <math.h>
#include <stdint.h>

// ---------------- problem constants ----------------
#define NTOK  4096
#define LSEQ  1024
#define BATCH 4
#define DM    1024
#define DI    2048
#define DS    16
#define DTR   64
#define XPD   96
#define NEXP  8
#define HEXP  1024
#define KSPL  8

// ---------------- device scratch ----------------
__device__ float g_x [NTOK*DM];
__device__ float g_uz[NTOK*2*DI];
__device__ float g_xp[NTOK*XPD];
__device__ float g_xps[KSPL*NTOK*XPD];
__device__ float g_dt[NTOK*DI];
__device__ float g_pp[2*NTOK*DM];
__device__ float g_mask[NTOK];
__device__ float g_pooled[BATCH*DM];
__device__ int   g_eidx[NTOK];
__device__ float g_ew  [NTOK];
__device__ int   g_perm[NTOK];
__device__ int   g_cnt[NEXP], g_off[NEXP], g_fill[NEXP], g_cntb[BATCH];
__device__ int   g_tk1, g_tk2, g_ntile;
__device__ int   g_tlist[64];

// fp16 hi/lo split buffers (activations only)
__device__ __half g_xh[NTOK*DM],  g_xl[NTOK*DM];
__device__ __half g_uh[NTOK*DI],  g_ul[NTOK*DI];
__device__ __half g_yh[NTOK*DI],  g_yl[NTOK*DI];
__device__ __half g_hh[NTOK*HEXP],g_hl[NTOK*HEXP];
__device__ __half g_dah[NTOK*DTR],g_dal[NTOK*DTR];

// ---------------- PTX helpers (base ISA only) ----------------
__device__ __forceinline__ uint32_t smem_u32(const void* p) {
    uint32_t a;
    asm("{ .reg .u64 t; cvta.to.shared.u64 t, %1; cvt.u32.u64 %0, t; }" : "=r"(a) : "l"(p));
    return a;
}
__device__ __forceinline__ void ldsm4(uint32_t* r, uint32_t addr) {
    asm volatile("ldmatrix.sync.aligned.m8n8.x4.shared.b16 {%0,%1,%2,%3}, [%4];"
        : "=r"(r[0]), "=r"(r[1]), "=r"(r[2]), "=r"(r[3]) : "r"(addr));
}
__device__ __forceinline__ void mma_f16(float* c, const uint32_t* a, uint32_t b0, uint32_t b1) {
    asm volatile("mma.sync.aligned.m16n8k16.row.col.f32.f16.f16.f32 "
        "{%0,%1,%2,%3}, {%4,%5,%6,%7}, {%8,%9}, {%0,%1,%2,%3};"
        : "+f"(c[0]), "+f"(c[1]), "+f"(c[2]), "+f"(c[3])
        : "r"(a[0]), "r"(a[1]), "r"(a[2]), "r"(a[3]), "r"(b0), "r"(b1));
}
__device__ __forceinline__ void cpa16(uint32_t saddr, const void* g, bool v) {
    int sz = v ? 16 : 0;
    asm volatile("cp.async.cg.shared.global [%0], [%1], 16, %2;"
        :: "r"(saddr), "l"(g), "r"(sz));
}
__device__ __forceinline__ void cpa16f(uint32_t saddr, const void* g) {
    asm volatile("cp.async.cg.shared.global [%0], [%1], 16;"
        :: "r"(saddr), "l"(g));
}
#define CP_COMMIT() asm volatile("cp.async.commit_group;" ::: "memory")
#define CP_WAIT1()  asm volatile("cp.async.wait_group 1;" ::: "memory")
#define CP_WAIT0()  asm volatile("cp.async.wait_group 0;" ::: "memory")

// smem geometry: K-chunk 32 fp16 = 64B/row, padded to 80B
#define ROWB   80
#define TILEB  10240
#define STAGEB 40960
#define SM_TOT 81920

// ---------------- shared GEMM body (expects locals: e,M,base,m0,n0,use3,sb,tid,
//  mode,N,K,lda,ldw,wz,ldc,czs,ks,act + pointer args in scope; defines acc + epilogue) ----
#define GEMM_BODY(Ah, Al, W32, C, Ch, Cl, bias, bias_z, perm, rowscale)                     \
    int sub = tid & 3;                                                                      \
    int r0 = tid >> 2;                                                                      \
    size_t aoff[2]; uint32_t avm = 0;                                                       \
    _Pragma("unroll")                                                                       \
    for (int i = 0; i < 2; i++) {                                                           \
        int mm = m0 + r0 + 64 * i;                                                          \
        bool av = mm < M;                                                                   \
        if (av) avm |= 1u << i;                                                             \
        int ar;                                                                             \
        if (mode == 1)      ar = av ? perm[base + mm] : 0;                                  \
        else if (mode == 2) ar = base + (av ? mm : 0);                                      \
        else                ar = av ? mm : 0;                                               \
        aoff[i] = (size_t)ar * lda + sub * 8 + (size_t)ks * K;                              \
    }                                                                                       \
    uint32_t srow0 = r0 * ROWB + sub * 16;                                                  \
    uint32_t srow1 = (r0 + 64) * ROWB + sub * 16;                                           \
    int wrow_l = tid >> 1;                                                                  \
    int wn = n0 + wrow_l;                                                                   \
    if (wn >= N) wn = 0;                                                                    \
    int khalf = (tid & 1) * 16;                                                             \
    const float* WE = W32 + (size_t)e * wz + (size_t)wn * ldw + khalf + (size_t)ks * K;     \
    uint32_t wsts = (uint32_t)wrow_l * ROWB + (tid & 1) * 32;                               \
    const int NC = K / 32;                                                                  \
    float4 wr[4];                                                                           \
    int lane = tid & 31;                                                                    \
    int wid = tid >> 5;                                                                     \
    int wm = (wid & 3) * 32;                                                                \
    int wn2 = (wid >> 2) * 64;                                                              \
    uint32_t aRB = (uint32_t)(wm + (lane & 7) + ((lane >> 3) & 1) * 8) * ROWB + ((lane >> 4) & 1) * 16; \
    uint32_t bRB = (uint32_t)(wn2 + (lane & 7) + ((lane >> 4) & 1) * 8) * ROWB + ((lane >> 3) & 1) * 16; \
    float acc[2][8][4] = {};                                                                \
    { int _k0 = 0;                                                                          \
      uint32_t _sB = sb;                                                                    \
      cpa16(_sB + srow0,         Ah + aoff[0] + _k0, avm & 1);                              \
      cpa16(_sB + srow1,         Ah + aoff[1] + _k0, (avm >> 1) & 1);                       \
      cpa16(_sB + TILEB + srow0, Al + aoff[0] + _k0, avm & 1);                              \
      cpa16(_sB + TILEB + srow1, Al + aoff[1] + _k0, (avm >> 1) & 1); }                     \
    CP_COMMIT();                                                                            \
    { const float4* _wp = reinterpret_cast<const float4*>(WE);                              \
      wr[0] = _wp[0]; wr[1] = _wp[1]; wr[2] = _wp[2]; wr[3] = _wp[3]; }                     \
    for (int c = 0; c < NC; c++) {                                                          \
        if (c + 1 < NC) {                                                                   \
            int _k0 = (c + 1) * 32;                                                         \
            uint32_t _sB = sb + (uint32_t)((c + 1) & 1) * STAGEB;                           \
            cpa16(_sB + srow0,         Ah + aoff[0] + _k0, avm & 1);                        \
            cpa16(_sB + srow1,         Ah + aoff[1] + _k0, (avm >> 1) & 1);                 \
            cpa16(_sB + TILEB + srow0, Al + aoff[0] + _k0, avm & 1);                        \
            cpa16(_sB + TILEB + srow1, Al + aoff[1] + _k0, (avm >> 1) & 1);                 \
            CP_COMMIT();                                                                    \
        }                                                                                   \
        {   float _wv[16];                                                                  \
            *(float4*)&_wv[0] = wr[0]; *(float4*)&_wv[4] = wr[1];                           \
            *(float4*)&_wv[8] = wr[2]; *(float4*)&_wv[12] = wr[3];                          \
            __half _hh[16];                                                                 \
            _Pragma("unroll")                                                               \
            for (int _i = 0; _i < 16; _i++) _hh[_i] = __float2half_rn(_wv[_i]);             \
            char* _wh = smem + (uint32_t)(c & 1) * STAGEB + 2 * TILEB + wsts;               \
            *(uint4*)(_wh)      = *(uint4*)&_hh[0];                                         \
            *(uint4*)(_wh + 16) = *(uint4*)&_hh[8];                                         \
            if (use3) {                                                                     \
                __half _hl[16];                                                             \
                _Pragma("unroll")                                                           \
                for (int _i = 0; _i < 16; _i++)                                             \
                    _hl[_i] = __float2half_rn(_wv[_i] - __half2float(_hh[_i]));             \
                char* _wl = smem + (uint32_t)(c & 1) * STAGEB + 3 * TILEB + wsts;           \
                *(uint4*)(_wl)      = *(uint4*)&_hl[0];                                     \
                *(uint4*)(_wl + 16) = *(uint4*)&_hl[8];                                     \
            }                                                                               \
        }                                                                                   \
        if (c + 1 < NC) CP_WAIT1(); else CP_WAIT0();                                        \
        __syncthreads();                                                                    \
        if (c + 1 < NC) {                                                                   \
            const float4* _wp = reinterpret_cast<const float4*>(WE + (size_t)(c + 1) * 32); \
            wr[0] = _wp[0]; wr[1] = _wp[1]; wr[2] = _wp[2]; wr[3] = _wp[3];                 \
        }                                                                                   \
        uint32_t AhB = sb + (uint32_t)(c & 1) * STAGEB;                                     \
        uint32_t AlB = AhB + TILEB;                                                         \
        uint32_t WhB = AhB + 2 * TILEB;                                                     \
        uint32_t WlB = AhB + 3 * TILEB;                                                     \
        _Pragma("unroll")                                                                   \
        for (int st = 0; st < 2; st++) {                                                    \
            uint32_t kB = st * 32;                                                          \
            uint32_t ah[2][4], al[2][4], bb[4][4];                                          \
            _Pragma("unroll")                                                               \
            for (int im = 0; im < 2; im++)                                                  \
                ldsm4(ah[im], AhB + (uint32_t)(im * 16) * ROWB + aRB + kB);                 \
            _Pragma("unroll")                                                               \
            for (int g2 = 0; g2 < 4; g2++)                                                  \
                ldsm4(bb[g2], WhB + (uint32_t)(g2 * 16) * ROWB + bRB + kB);                 \
            _Pragma("unroll")                                                               \
            for (int im = 0; im < 2; im++)                                                  \
                _Pragma("unroll")                                                           \
                for (int in = 0; in < 8; in++)                                              \
                    mma_f16(acc[im][in], ah[im], bb[in >> 1][(in & 1) * 2], bb[in >> 1][(in & 1) * 2 + 1]); \
            _Pragma("unroll")                                                               \
            for (int im = 0; im < 2; im++)                                                  \
                ldsm4(al[im], AlB + (uint32_t)(im * 16) * ROWB + aRB + kB);                 \
            _Pragma("unroll")                                                               \
            for (int im = 0; im < 2; im++)                                                  \
                _Pragma("unroll")                                                           \
                for (int in = 0; in < 8; in++)                                              \
                    mma_f16(acc[im][in], al[im], bb[in >> 1][(in & 1) * 2], bb[in >> 1][(in & 1) * 2 + 1]); \
            if (use3) {                                                                     \
                _Pragma("unroll")                                                           \
                for (int g2 = 0; g2 < 4; g2++)                                              \
                    ldsm4(bb[g2], WlB + (uint32_t)(g2 * 16) * ROWB + bRB + kB);             \
                _Pragma("unroll")                                                           \
                for (int im = 0; im < 2; im++)                                              \
                    _Pragma("unroll")                                                       \
                    for (int in = 0; in < 8; in++)                                          \
                        mma_f16(acc[im][in], ah[im], bb[in >> 1][(in & 1) * 2], bb[in >> 1][(in & 1) * 2 + 1]); \
            }                                                                               \
        }                                                                                   \
        __syncthreads();                                                                    \
    }                                                                                       \
    int lq = lane >> 2;                                                                     \
    int lr = lane & 3;                                                                      \
    const float* bp = (bias && ks == 0) ? (bias + (size_t)e * bias_z) : nullptr;            \
    float* Cz = C ? (C + (size_t)ks * czs) : C;                                             \
    _Pragma("unroll")                                                                       \
    for (int im = 0; im < 2; im++) {                                                        \
        _Pragma("unroll")                                                                   \
        for (int r2 = 0; r2 < 2; r2++) {                                                    \
            int m = m0 + wm + im * 16 + lq + r2 * 8;                                        \
            if (m >= M) continue;                                                           \
            long crow; float scale = 1.f;                                                   \
            if (mode == 2)      { crow = perm[base + m]; scale = rowscale[crow]; }          \
            else if (mode == 1) { crow = base + m; }                                        \
            else                { crow = m; }                                               \
            _Pragma("unroll")                                                               \
            for (int in = 0; in < 8; in++) {                                                \
                int n = n0 + wn2 + in * 8 + lr * 2;                                         \
                if (n >= N) continue;                                                       \
                float v0 = acc[im][in][r2 * 2 + 0];                                         \
                float v1 = acc[im][in][r2 * 2 + 1];                                         \
                if (bp) { v0 += bp[n]; v1 += bp[n + 1]; }                                   \
                if (act == 1) { v0 = fmaxf(v0, 0.f); v1 = fmaxf(v1, 0.f); }                 \
                else if (act == 2) {                                                        \
                    v0 = (v0 > 20.f) ? v0 : log1pf(__expf(v0));                             \
                    v1 = (v1 > 20.f) ? v1 : log1pf(__expf(v1));                             \
                }                                                                           \
                if (Ch) {                                                                   \
                    __half h0 = __float2half_rn(v0);                                        \
                    __half h1 = __float2half_rn(v1);                                        \
                    size_t o = (size_t)crow * ldc + n;                                      \
                    Ch[o] = h0;     Cl[o]     = __float2half_rn(v0 - __half2float(h0));     \
                    Ch[o + 1] = h1; Cl[o + 1] = __float2half_rn(v1 - __half2float(h1));     \
                } else {                                                                    \
                    size_t o = (size_t)crow * ldc + n;                                      \
                    Cz[o] = v0 * scale;                                                     \
                    Cz[o + 1] = v1 * scale;                                                 \
                }                                                                           \
            }                                                                               \
        }                                                                                   \
    }

// ============ dense fused-split fp16 mma.sync GEMM ============
__global__ void __launch_bounds__(256, 2)
mma_gemm(const __half* __restrict__ Ah, const __half* __restrict__ Al, int lda,
         const float* __restrict__ W32, int ldw, size_t wz,
         float* __restrict__ C, int ldc, size_t czs,
         __half* __restrict__ Ch, __half* __restrict__ Cl,
         const float* __restrict__ bias, int bias_z,
         int M_fixed, const int* __restrict__ perm, const float* __restrict__ rowscale,
         int mode, int N, int K, int nyb, int act, int terms, int t3lim)
{
    int e = blockIdx.z;
    int M = M_fixed;
    int base = 0;
    int yy = blockIdx.y;
    int ks = yy / nyb;
    int nb = yy - ks * nyb;
    int bx = blockIdx.x;

    // raster swizzle: 4-wide m-supertiles for L2 locality
    {
        int nbx = gridDim.x;
        if (nbx >= 4) {
            int lin = nb * nbx + bx;
            int sw = 4 * nyb;
            int stile = lin / sw;
            int rem = lin - stile * sw;
            int m_in = rem % 4;
            int n_in = rem / 4;
            int mb = stile * 4 + m_in;
            if (mb < nbx) { bx = mb; nb = n_in; }
        }
    }

    int m0 = bx * 128;
    if (m0 >= M) return;
    int n0 = nb * 128;
    int use3 = (terms == 3) && (n0 < t3lim);

    extern __shared__ char smem[];
    uint32_t sb = smem_u32(smem);
    int tid = threadIdx.x;

    GEMM_BODY(Ah, Al, W32, C, Ch, Cl, bias, bias_z, perm, rowscale)
}

// ============ persistent ticket-scheduled MoE GEMM (no-op-free tiles) ============
// work item t in [0, g_ntile*16): list entry t>>4 gives (expert, m-block); yy = t&15 -> (ks, nb).
__global__ void __launch_bounds__(256, 2)
mma_gemm_moe(const __half* __restrict__ Ah, const __half* __restrict__ Al, int lda,
             const float* __restrict__ W32, int ldw, size_t wz,
             float* __restrict__ C, int ldc, size_t czs,
             __half* __restrict__ Ch, __half* __restrict__ Cl,
             const float* __restrict__ bias, int bias_z,
             const int* __restrict__ cntp, const int* __restrict__ offp,
             const int* __restrict__ perm, const float* __restrict__ rowscale,
             int mode, int N, int K, int act, int terms, int* ticket)
{
    extern __shared__ char smem[];
    uint32_t sb = smem_u32(smem);
    int tid = threadIdx.x;
    __shared__ int s_t;
    int use3 = (terms == 3);

    while (true) {
        if (tid == 0) s_t = atomicAdd(ticket, 1);
        __syncthreads();
        int t = s_t;
        if (t >= g_ntile * 16) break;       // nyb(8) * ksplit(2)
        int ent = g_tlist[t >> 4];
        int yy = t & 15;
        int e = ent >> 8;
        int m0 = (ent & 255) * 128;
        int ks = yy >> 3;
        int nb = yy & 7;
        int n0 = nb * 128;
        int M = cntp[e];
        int base = offp[e];
        if (m0 < M) {
            GEMM_BODY(Ah, Al, W32, C, Ch, Cl, bias, bias_z, perm, rowscale)
        }
        __syncthreads();   // all reads of s_t / smem done before next iteration's write
    }
}

// ---------------- fp16 split helpers ----------------
__device__ __forceinline__ void split2(float v, __half& h, __half& l) {
    h = __float2half_rn(v);
    l = __float2half_rn(v - __half2float(h));
}

// fused split-K reduce for xp + dt-input conversion
__global__ void xp_reduce_dt_k() {
    int i = blockIdx.x * 256 + threadIdx.x;
    float s = 0.f;
#pragma unroll
    for (int j = 0; j < KSPL; j++) s += g_xps[(size_t)j * NTOK * XPD + i];
    g_xp[i] = s;
    int t = i / XPD, c = i - t * XPD;
    if (c < DTR) {
        int o = t * DTR + c;
        split2(s, g_dah[o], g_dal[o]);
    }
}

// ---------------- embed ----------------
__global__ void embed_k(const int* __restrict__ tok, const float* __restrict__ emb,
                        const float* __restrict__ pos) {
    int i = blockIdx.x * blockDim.x + threadIdx.x;
    int t = i / DM, d = i % DM;
    int l = t % LSEQ;
    float v = emb[(size_t)tok[t] * DM + d] + pos[l * DM + d];
    g_x[i] = v;
    split2(v, g_xh[i], g_xl[i]);
}

// ---------------- smem-tiled conv + silu -> fp16 pair ----------------
__global__ void __launch_bounds__(256) conv_silu_k(const float* __restrict__ cw,
                                                   const float* __restrict__ cb) {
    __shared__ float sm[67][128];
    int tokb = blockIdx.x * 64;
    int d0 = blockIdx.y * 128;
    int tid = threadIdx.x;
    int bstart = (tokb / LSEQ) * LSEQ;

    for (int i = tid; i < 67 * 128; i += 256) {
        int r = i >> 7, dcol = i & 127;
        int tr = tokb - 3 + r;
        sm[r][dcol] = (tr >= bstart) ? g_uz[(size_t)tr * (2 * DI) + d0 + dcol] : 0.f;
    }
    __syncthreads();

    int dcol = tid & 127;
    int d = d0 + dcol;
    float4 w4 = *(const float4*)(cw + d * 4);
    float bv = cb[d];
    int sbase = tid >> 7;
#pragma unroll
    for (int it = 0; it < 32; it++) {
        int s = sbase + it * 2;
        float acc = bv + sm[s][dcol] * w4.x + sm[s + 1][dcol] * w4.y
                       + sm[s + 2][dcol] * w4.z + sm[s + 3][dcol] * w4.w;
        float v = acc / (1.f + __expf(-acc));
        size_t o = (size_t)(tokb + s) * DI + d;
        split2(v, g_uh[o], g_ul[o]);
    }
}

// ---------------- A structure detection ----------------
__device__ __forceinline__ bool load_A(const float* A_log, int d, float* A) {
    bool fast = true;
#pragma unroll
    for (int n = 0; n < DS; n++) {
        A[n] = -expf(A_log[d * DS + n]);
        fast = fast && (fabsf(A[n] + (float)(n + 1)) < 1e-4f);
    }
    return fast;
}

// ---------------- single-pass selective scan with cp.async staging ----------------
#define SC_CH   32
#define SC_NC   (LSEQ / SC_CH)
#define SC_UH   0
#define SC_UL   16384
#define SC_DT   32768
#define SC_Z    65536
#define SC_B    98304
#define SC_C    102400
#define SC_SMEM 106496

__global__ void __launch_bounds__(128) ssm_scan_k(const float* __restrict__ A_log,
                                                  const float* __restrict__ Dp) {
    int b = blockIdx.x;
    int d0 = blockIdx.y * 128;
    int tid = threadIdx.x;
    int d = d0 + tid;

    float A[DS];
    bool fast = load_A(A_log, d, A);
    float Dv = Dp[d];
    float h[DS];
#pragma unroll
    for (int n = 0; n < DS; n++) h[n] = 0.f;

    extern __shared__ char smc[];
    uint32_t sbase = smem_u32(smc);

#define SC_ISSUE(c) do { \
        int _buf = (c) & 1; \
        int _tokb = b * LSEQ + (c) * SC_CH; \
        _Pragma("unroll") \
        for (int _j = 0; _j < 4; _j++) { \
            int _q = _j * 128 + tid; \
            int _s = _q >> 4, _hq = (_q & 15) * 8; \
            uint32_t _o = (uint32_t)(_buf * 8192 + _s * 256 + _hq * 2); \
            cpa16f(sbase + SC_UH + _o, g_uh + (size_t)(_tokb + _s) * DI + d0 + _hq); \
            cpa16f(sbase + SC_UL + _o, g_ul + (size_t)(_tokb + _s) * DI + d0 + _hq); \
        } \
        _Pragma("unroll") \
        for (int _j = 0; _j < 8; _j++) { \
            int _q = _j * 128 + tid; \
            int _s = _q >> 5, _qd = (_q & 31) * 4; \
            uint32_t _o = (uint32_t)(_buf * 16384 + _s * 512 + _qd * 4); \
            cpa16f(sbase + SC_DT + _o, g_dt + (size_t)(_tokb + _s) * DI + d0 + _qd); \
            cpa16f(sbase + SC_Z  + _o, g_uz + (size_t)(_tokb + _s) * (2 * DI) + DI + d0 + _qd); \
        } \
        { int _s = tid >> 2, _qd = (tid & 3) * 4; \
          uint32_t _o = (uint32_t)(_buf * 2048 + _s * 64 + _qd * 4); \
          cpa16f(sbase + SC_B + _o, g_xp + (size_t)(_tokb + _s) * XPD + DTR + _qd); \
          cpa16f(sbase + SC_C + _o, g_xp + (size_t)(_tokb + _s) * XPD + DTR + DS + _qd); } \
        CP_COMMIT(); \
    } while (0)

    SC_ISSUE(0);
    for (int c = 0; c < SC_NC; c++) {
        if (c + 1 < SC_NC) SC_ISSUE(c + 1);
        if (c + 1 < SC_NC) CP_WAIT1(); else CP_WAIT0();
        __syncthreads();
        int buf = c & 1;
        int tokb = b * LSEQ + c * SC_CH;
        const __half* suh = (const __half*)(smc + SC_UH + buf * 8192) + tid;
        const __half* sul = (const __half*)(smc + SC_UL + buf * 8192) + tid;
        const float* sd = (const float*)(smc + SC_DT + buf * 16384) + tid;
        const float* sz = (const float*)(smc + SC_Z  + buf * 16384) + tid;
        const float* sB = (const float*)(smc + SC_B + buf * 2048);
        const float* sC = (const float*)(smc + SC_C + buf * 2048);
        if (fast) {
            for (int s = 0; s < SC_CH; s++) {
                float ut  = __half2float(suh[s * 128]) + __half2float(sul[s * 128]);
                float dtt = sd[s * 128];
                float z   = sz[s * 128];
                float du = dtt * ut;
                float e1 = __expf(-dtt);
                float e2 = e1 * e1, e3 = e2 * e1, e4 = e2 * e2;
                float e8 = e4 * e4, e12 = e8 * e4;
                float pw[DS] = {e1, e2, e3, e4,
                                e4 * e1, e4 * e2, e4 * e3, e8,
                                e8 * e1, e8 * e2, e8 * e3, e12,
                                e12 * e1, e12 * e2, e12 * e3, e8 * e8};
                float yv = 0.f;
#pragma unroll
                for (int n = 0; n < DS; n++) {
                    h[n] = pw[n] * h[n] + du * sB[s * 16 + n];
                    yv += h[n] * sC[s * 16 + n];
                }
                yv += ut * Dv;
                float y = yv * (z / (1.f + __expf(-z)));
                size_t o = (size_t)(tokb + s) * DI + d;
                split2(y, g_yh[o], g_yl[o]);
            }
        } else {
            for (int s = 0; s < SC_CH; s++) {
                float ut  = __half2float(suh[s * 128]) + __half2float(sul[s * 128]);
                float dtt = sd[s * 128];
                float z   = sz[s * 128];
                float du = dtt * ut;
                float yv = 0.f;
#pragma unroll
                for (int n = 0; n < DS; n++) {
                    h[n] = __expf(dtt * A[n]) * h[n] + du * sB[s * 16 + n];
                    yv += h[n] * sC[s * 16 + n];
                }
                yv += ut * Dv;
                float y = yv * (z / (1.f + __expf(-z)));
                size_t o = (size_t)(tokb + s) * DI + d;
                split2(y, g_yh[o], g_yl[o]);
            }
        }
        __syncthreads();
    }
#undef SC_ISSUE
}

// ---------------- x += LayerNorm(t0 + t1); optional fused gate / rowmask ----------------
__global__ void addln_k(const float* __restrict__ g, const float* __restrict__ bb,
                        const float* __restrict__ t0, const float* __restrict__ t1,
                        const float* __restrict__ gw, const float* __restrict__ gb,
                        int cntb_rst, int do_mask) {
    int tok = blockIdx.x;
    int tid = threadIdx.x;
    if (gw && tok == 0 && tid < NEXP) { g_cnt[tid] = 0; g_fill[tid] = 0; }
    if (cntb_rst && tok == 0 && tid < BATCH) g_cntb[tid] = 0;
    float* x = g_x + (size_t)tok * DM;
    float v[4]; float s = 0.f;
#pragma unroll
    for (int i = 0; i < 4; i++) {
        size_t o = (size_t)tok * DM + tid + i * 256;
        v[i] = t0[o] + t1[o];
        s += v[i];
    }
    __shared__ float sm[256];
    sm[tid] = s; __syncthreads();
    for (int st = 128; st > 0; st >>= 1) { if (tid < st) sm[tid] += sm[tid + st]; __syncthreads(); }
    float mean = sm[0] / DM;
    __syncthreads();
    float q = 0.f;
#pragma unroll
    for (int i = 0; i < 4; i++) { float dd = v[i] - mean; q += dd * dd; }
    sm[tid] = q; __syncthreads();
    for (int st = 128; st > 0; st >>= 1) { if (tid < st) sm[tid] += sm[tid + st]; __syncthreads(); }
    float rstd = rsqrtf(sm[0] / DM + 1e-5f);

    float nx[4]; float s2 = 0.f;
#pragma unroll
    for (int i = 0; i < 4; i++) {
        int d = tid + i * 256;
        nx[i] = x[d] + (v[i] - mean) * rstd * g[d] + bb[d];
        x[d] = nx[i];
        s2 += nx[i];
        split2(nx[i], g_xh[(size_t)tok * DM + d], g_xl[(size_t)tok * DM + d]);
    }

    if (do_mask) {
        __syncthreads();
        sm[tid] = s2; __syncthreads();
        for (int st = 128; st > 0; st >>= 1) { if (tid < st) sm[tid] += sm[tid + st]; __syncthreads(); }
        if (tid == 0) {
            float m = (sm[0] != 0.f) ? 1.f : 0.f;
            g_mask[tok] = m;
            if (m != 0.f) atomicAdd(&g_cntb[tok / LSEQ], 1);
        }
    }

    if (gw) {
        __shared__ float gsm[NEXP][256];
        float p[NEXP];
#pragma unroll
        for (int e = 0; e < NEXP; e++) p[e] = 0.f;
#pragma unroll
        for (int i = 0; i < 4; i++) {
            int d = tid + i * 256;
            float xv = nx[i];
#pragma unroll
            for (int e = 0; e < NEXP; e++) p[e] += xv * gw[e * DM + d];
        }
        __syncthreads();
#pragma unroll
        for (int e = 0; e < NEXP; e++) gsm[e][tid] = p[e];
        __syncthreads();
        for (int st = 128; st > 0; st >>= 1) {
            if (tid < st)
#pragma unroll
                for (int e = 0; e < NEXP; e++) gsm[e][tid] += gsm[e][tid + st];
            __syncthreads();
        }
        if (tid == 0) {
            float m = -1e30f; int bi = 0;
            float lg[NEXP];
#pragma unroll
            for (int e = 0; e < NEXP; e++) {
                lg[e] = gsm[e][0] + gb[e];
                if (lg[e] > m) { m = lg[e]; bi = e; }
            }
            float ssum = 0.f;
#pragma unroll
            for (int e = 0; e < NEXP; e++) ssum += __expf(lg[e] - m);
            g_eidx[tok] = bi;
            g_ew[tok] = 1.f / ssum;
            atomicAdd(&g_cnt[bi], 1);
        }
    }
}

// ---------------- moe1 combine ----------------
__global__ void moe1_comb(const float* __restrict__ b1) {
    int i = blockIdx.x * 256 + threadIdx.x;
    int r = i >> 10, col = i & 1023;
    int e = g_eidx[g_perm[r]];
    float v = g_pp[i] + g_pp[NTOK * HEXP + i] + b1[e * HEXP + col];
    v = fmaxf(v, 0.f);
    split2(v, g_hh[i], g_hl[i]);
}

// offsets + MoE tile list + ticket reset
__global__ void route_offsets_k() {
    if (threadIdx.x == 0) {
        int o = 0, k = 0;
        for (int e = 0; e < NEXP; e++) {
            g_off[e] = o; o += g_cnt[e];
            int nt = (g_cnt[e] + 127) >> 7;
            for (int mb = 0; mb < nt; mb++) g_tlist[k++] = (e << 8) | mb;
        }
        g_ntile = k;
        g_tk1 = 0;
        g_tk2 = 0;
    }
}
__global__ void route_scatter_k() {
    int tok = blockIdx.x * 256 + threadIdx.x;
    if (tok < NTOK) {
        int e = g_eidx[tok];
        int p = g_off[e] + atomicAdd(&g_fill[e], 1);
        g_perm[p] = tok;
    }
}

// ---------------- pooling + head ----------------
__global__ void pool_k() {
    int b = blockIdx.x;
    int d = blockIdx.y * 256 + threadIdx.x;
    float acc = 0.f;
    for (int l = 0; l < LSEQ; l++)
        acc += g_x[(size_t)(b * LSEQ + l) * DM + d] * g_mask[b * LSEQ + l];
    g_pooled[b * DM + d] = acc / fmaxf((float)g_cntb[b], 1.f);
}

__global__ void head_k(const float* __restrict__ w1, const float* __restrict__ b1,
                       const float* __restrict__ w2, const float* __restrict__ b2,
                       float* __restrict__ out) {
    int b = blockIdx.x;
    int j = threadIdx.x;
    const float* p = g_pooled + b * DM;
    float acc = b1[j];
    for (int k = 0; k < DM; k++) acc += p[k] * w1[j * DM + k];
    __shared__ float h[128];
    h[j] = fmaxf(acc, 0.f);
    __syncthreads();
    if (j < 2) {
        float o = b2[j];
        for (int k = 0; k < 128; k++) o += h[k] * w2[j * 128 + k];
        out[b * 2 + j] = o;
    }
}

// ---------------- launch ----------------
extern "C" void kernel_launch(void* const* d_in, const int* in_sizes, int n_in,
                              void* d_out, int out_size) {
    const int*   tok    = (const int*)  d_in[0];
    const float* emb    = (const float*)d_in[1];
    const float* pos    = (const float*)d_in[2];
    const float* in_w   = (const float*)d_in[3];
    const float* conv_w = (const float*)d_in[4];
    const float* conv_b = (const float*)d_in[5];
    const float* xp_w   = (const float*)d_in[6];
    const float* dt_w   = (const float*)d_in[7];
    const float* dt_b   = (const float*)d_in[8];
    const float* A_log  = (const float*)d_in[9];
    const float* D_ssm  = (const float*)d_in[10];
    const float* out_w  = (const float*)d_in[11];
    const float* ln1_g  = (const float*)d_in[12];
    const float* ln1_b  = (const float*)d_in[13];
    const float* ln2_g  = (const float*)d_in[14];
    const float* ln2_b  = (const float*)d_in[15];
    const float* gate_w = (const float*)d_in[16];
    const float* gate_b = (const float*)d_in[17];
    const float* e_w1   = (const float*)d_in[18];
    const float* e_b1   = (const float*)d_in[19];
    const float* e_w2   = (const float*)d_in[20];
    const float* e_b2   = (const float*)d_in[21];
    const float* fc1_w  = (const float*)d_in[22];
    const float* fc1_b  = (const float*)d_in[23];
    const float* fc2_w  = (const float*)d_in[24];
    const float* fc2_b  = (const float*)d_in[25];
    float* out = (float*)d_out;

    cudaFuncSetAttribute(mma_gemm, cudaFuncAttributeMaxDynamicSharedMemorySize, SM_TOT);
    cudaFuncSetAttribute(mma_gemm_moe, cudaFuncAttributeMaxDynamicSharedMemorySize, SM_TOT);
    cudaFuncSetAttribute(ssm_scan_k, cudaFuncAttributeMaxDynamicSharedMemorySize, SC_SMEM);

    float *puz, *pxps, *pdt, *ppp, *pew;
    __half *pxh, *pxl, *puh, *pul, *pyh, *pyl, *phh, *phl, *pdah, *pdal;
    int *pcnt, *poff, *pperm, *ptk1, *ptk2;
    cudaGetSymbolAddress((void**)&puz,  g_uz);
    cudaGetSymbolAddress((void**)&pxps, g_xps);
    cudaGetSymbolAddress((void**)&pdt,  g_dt);
    cudaGetSymbolAddress((void**)&ppp,  g_pp);
    cudaGetSymbolAddress((void**)&pew,  g_ew);
    cudaGetSymbolAddress((void**)&pxh,  g_xh);
    cudaGetSymbolAddress((void**)&pxl,  g_xl);
    cudaGetSymbolAddress((void**)&puh,  g_uh);
    cudaGetSymbolAddress((void**)&pul,  g_ul);
    cudaGetSymbolAddress((void**)&pyh,  g_yh);
    cudaGetSymbolAddress((void**)&pyl,  g_yl);
    cudaGetSymbolAddress((void**)&phh,  g_hh);
    cudaGetSymbolAddress((void**)&phl,  g_hl);
    cudaGetSymbolAddress((void**)&pdah, g_dah);
    cudaGetSymbolAddress((void**)&pdal, g_dal);
    cudaGetSymbolAddress((void**)&pcnt, g_cnt);
    cudaGetSymbolAddress((void**)&poff, g_off);
    cudaGetSymbolAddress((void**)&pperm,g_perm);
    cudaGetSymbolAddress((void**)&ptk1, g_tk1);
    cudaGetSymbolAddress((void**)&ptk2, g_tk2);

    const int BIG = 1 << 30;

    embed_k<<<(NTOK * DM) / 256, 256>>>(tok, emb, pos);

    for (int l = 0; l < 2; l++) {
        const float* in_w_l  = in_w  + (size_t)l * 2 * DI * DM;
        const float* xp_w_l  = xp_w  + (size_t)l * XPD * DI;
        const float* dt_w_l  = dt_w  + (size_t)l * DI * DTR;
        const float* out_w_l = out_w + (size_t)l * DM * DI;
        const float* e_w1_l  = e_w1  + (size_t)l * NEXP * HEXP * DM;
        const float* e_w2_l  = e_w2  + (size_t)l * NEXP * DM * HEXP;
        const float* A_log_l = A_log + (size_t)l * DI * DS;
        int t2 = (l == 1) ? 2 : 3;
        int in_t3lim = (l == 1) ? DI : BIG;

        // in_proj (u-half always 3-term: feeds the scan path)
        mma_gemm<<<dim3(32, 32, 1), 256, SM_TOT>>>(
            pxh, pxl, DM, in_w_l, DM, 0, puz, 2 * DI, 0, nullptr, nullptr,
            nullptr, 0, NTOK, nullptr, nullptr, 0, 2 * DI, DM, 32, 0, 3, in_t3lim);

        conv_silu_k<<<dim3(NTOK / 64, DI / 128), 256>>>(conv_w + (size_t)l * DI * 4,
                                                        conv_b + (size_t)l * DI);

        // xp: split-K x8 (3-term)
        mma_gemm<<<dim3(32, KSPL, 1), 256, SM_TOT>>>(
            puh, pul, DI, xp_w_l, DI, 0, pxps, XPD, (size_t)NTOK * XPD, nullptr, nullptr,
            nullptr, 0, NTOK, nullptr, nullptr, 0, XPD, DI / KSPL, 1, 0, 3, BIG);
        xp_reduce_dt_k<<<(NTOK * XPD) / 256, 256>>>();

        // dt (3-term)
        mma_gemm<<<dim3(32, 16, 1), 256, SM_TOT>>>(
            pdah, pdal, DTR, dt_w_l, DTR, 0, pdt, DI, 0, nullptr, nullptr,
            dt_b + (size_t)l * DI, 0, NTOK, nullptr, nullptr, 0, DI, DTR, 16, 2, 3, BIG);

        // single-pass scan
        ssm_scan_k<<<dim3(BATCH, DI / 128), 128, SC_SMEM>>>(
            A_log_l, D_ssm + (size_t)l * DI);

        // out: split-K x2
        mma_gemm<<<dim3(32, 16, 1), 256, SM_TOT>>>(
            pyh, pyl, DI, out_w_l, DI, 0, ppp, DM, (size_t)NTOK * DM, nullptr, nullptr,
            nullptr, 0, NTOK, nullptr, nullptr, 0, DM, DI / 2, 8, 0, t2, BIG);

        // x += LN(out) with fused gate; on layer 2 also reset cntb for mask pass
        addln_k<<<NTOK, 256>>>(ln1_g + (size_t)l * DM, ln1_b + (size_t)l * DM,
                               ppp, ppp + (size_t)NTOK * DM,
                               gate_w + (size_t)l * NEXP * DM, gate_b + (size_t)l * NEXP,
                               (l == 1) ? 1 : 0, 0);

        route_offsets_k<<<1, 1>>>();
        route_scatter_k<<<NTOK / 256, 256>>>();

        // moe1: persistent ticket GEMM (split-K x2) + combine
        mma_gemm_moe<<<296, 256, SM_TOT>>>(
            pxh, pxl, DM, e_w1_l, DM, (size_t)HEXP * DM, ppp, HEXP, (size_t)NTOK * HEXP,
            nullptr, nullptr, nullptr, 0, pcnt, poff, pperm, nullptr,
            1, HEXP, DM / 2, 0, t2, ptk1);
        moe1_comb<<<(NTOK * HEXP) / 256, 256>>>(e_b1 + (size_t)l * NEXP * HEXP);

        // moe2: persistent ticket GEMM (split-K x2)
        mma_gemm_moe<<<296, 256, SM_TOT>>>(
            phh, phl, HEXP, e_w2_l, HEXP, (size_t)DM * HEXP, ppp, DM, (size_t)NTOK * DM,
            nullptr, nullptr, e_b2 + (size_t)l * NEXP * DM, DM, pcnt, poff, pperm, pew,
            2, DM, HEXP / 2, 0, t2, ptk2);

        // x += LN(moe); on last layer compute rowmask inline
        addln_k<<<NTOK, 256>>>(ln2_g + (size_t)l * DM, ln2_b + (size_t)l * DM,
                               ppp, ppp + (size_t)NTOK * DM, nullptr, nullptr,
                               0, (l == 1) ? 1 : 0);
    }

    pool_k<<<dim3(BATCH, DM / 256), 256>>>();
    head_k<<<BATCH, 128>>>(fc1_w, fc1_b, fc2_w, fc2_b, out);
}